// round 15
// baseline (speedup 1.0000x reference)
#include <cuda_runtime.h>
#include <math.h>

#define TLEN    2048
#define HEADS_N 8
#define BATCH   2
#define SDIM    64
#define EDIM    512
#define QE_BH   2162688   // 4096 * 528 floats per (b,h)
#define NCHUNK  144       // sum over it of ceil((it+1)/4)

// ---------------- scratch + resolved input pointers (device-resident) ----------
__device__ float g_q[BATCH*HEADS_N*TLEN*SDIM];
__device__ float g_k[BATCH*HEADS_N*TLEN*SDIM];
__device__ float g_v[BATCH*HEADS_N*TLEN*SDIM];
__device__ float g_vmean[BATCH*HEADS_N*SDIM];
__device__ float g_attn[BATCH*TLEN*EDIM];
__device__ float g_qe[BATCH*HEADS_N*QE_BH];   // triangular-packed QE bands
__device__ float g_pO[(size_t)BATCH*HEADS_N*NCHUNK*64*64];   // split-KV partials
__device__ float g_pm[BATCH*HEADS_N*NCHUNK*64];
__device__ float g_pl[BATCH*HEADS_N*NCHUNK*64];

__device__ const float*        g_pWq;
__device__ const float*        g_pWk;
__device__ const float*        g_pWv;
__device__ const unsigned int* g_pmask;

// ---------------- tf32 helpers ----------------
__device__ __forceinline__ unsigned int f2tf32(float x) {
    unsigned int r;
    asm("cvt.rna.tf32.f32 %0, %1;" : "=r"(r) : "f"(x));
    return r;
}
__device__ __forceinline__ float tf32r(float x) {   // round to tf32, as float
    return __uint_as_float(f2tf32(x));
}
__device__ __forceinline__ void mma_tf32(float d[4],
        unsigned int a0, unsigned int a1, unsigned int a2, unsigned int a3,
        unsigned int b0, unsigned int b1) {
    asm("mma.sync.aligned.m16n8k8.row.col.f32.tf32.tf32.f32 "
        "{%0,%1,%2,%3}, {%4,%5,%6,%7}, {%8,%9}, {%0,%1,%2,%3};"
        : "+f"(d[0]), "+f"(d[1]), "+f"(d[2]), "+f"(d[3])
        : "r"(a0), "r"(a1), "r"(a2), "r"(a3), "r"(b0), "r"(b1));
}

// ---------------- prologue: content-based identification of mask ---------------
__global__ void select_inputs(const float* c0, const float* c1,
                              const float* c2, const float* c3, int x_first) {
    __shared__ int bad[4];
    const float* cand[4] = {c0, c1, c2, c3};
    if (threadIdx.x < 4) bad[threadIdx.x] = 0;
    __syncthreads();
    for (int j = 0; j < 4; j++) {
        const unsigned int* p = (const unsigned int*)cand[j];
        int b = 0;
        for (int i = threadIdx.x; i < SDIM*SDIM; i += blockDim.x) {
            unsigned int v = p[i];
            if (v != 0u && v != 1u && v != 0x3F800000u) { b = 1; break; }
        }
        if (b) atomicOr(&bad[j], 1);
    }
    __syncthreads();
    if (threadIdx.x == 0) {
        int mi = -1;
        for (int j = 0; j < 4; j++) if (!bad[j]) { mi = j; break; }
        if (mi < 0) mi = x_first ? 0 : 3;
        const float* rest[3]; int n = 0;
        for (int j = 0; j < 4; j++) if (j != mi) rest[n++] = cand[j];
        g_pmask = (const unsigned int*)cand[mi];
        if (x_first) { g_pWq = rest[0]; g_pWk = rest[1]; g_pWv = rest[2]; }
        else         { g_pWk = rest[0]; g_pWq = rest[1]; g_pWv = rest[2]; }
    }
}

// ---------------- QKV projection via tf32 3x mma ----------------
__global__ void __launch_bounds__(256) proj_kernel(const float* __restrict__ x) {
    extern __shared__ float sm[];
    float* sX = sm;              // [row=128][k=64] fp32, stride 68
    float* sWh = sX + 128*68;    // [o=64][k] hi
    float* sWl = sWh + 64*68;    // lo

    const int m0 = blockIdx.x * 128;
    const int h  = blockIdx.y / 3;
    const int mm = blockIdx.y % 3;
    const int b  = blockIdx.z;
    const int tid = threadIdx.x;
    const float* W = (mm == 0) ? g_pWq : (mm == 1) ? g_pWk : g_pWv;
    float* dst = (mm == 0) ? g_q : (mm == 1) ? g_k : g_v;

    for (int k = tid; k < 2048; k += 256) {
        int row = k >> 4, i4 = (k & 15)*4;
        *(float4*)&sX[row*68 + i4] =
            *(const float4*)&x[(size_t)(b*TLEN + m0 + row)*EDIM + h*SDIM + i4];
    }
    for (int k = tid; k < 1024; k += 256) {
        int row = k >> 4, i4 = (k & 15)*4;
        float4 f = *(const float4*)&W[row*SDIM + i4];
        float hx = tf32r(f.x), hy = tf32r(f.y), hz = tf32r(f.z), hw = tf32r(f.w);
        *(float4*)&sWh[row*68 + i4] = make_float4(hx, hy, hz, hw);
        *(float4*)&sWl[row*68 + i4] = make_float4(
            tf32r(f.x - hx), tf32r(f.y - hy), tf32r(f.z - hz), tf32r(f.w - hw));
    }
    __syncthreads();

    const int w = tid >> 5, lane = tid & 31;
    const int g = lane >> 2, tg = lane & 3;
    const int mr = w*16 + g;

    float acc[8][4];
    #pragma unroll
    for (int nt = 0; nt < 8; nt++)
        #pragma unroll
        for (int i = 0; i < 4; i++) acc[nt][i] = 0.f;

    #pragma unroll
    for (int kk = 0; kk < 8; kk++) {
        const int k0 = kk*8;
        float q0 = sX[mr*68 + k0 + tg];
        float q1 = sX[(mr + 8)*68 + k0 + tg];
        float q2 = sX[mr*68 + k0 + tg + 4];
        float q3 = sX[(mr + 8)*68 + k0 + tg + 4];
        unsigned int ah0 = f2tf32(q0), ah1 = f2tf32(q1);
        unsigned int ah2 = f2tf32(q2), ah3 = f2tf32(q3);
        unsigned int al0 = f2tf32(q0 - __uint_as_float(ah0));
        unsigned int al1 = f2tf32(q1 - __uint_as_float(ah1));
        unsigned int al2 = f2tf32(q2 - __uint_as_float(ah2));
        unsigned int al3 = f2tf32(q3 - __uint_as_float(ah3));
        #pragma unroll
        for (int nt = 0; nt < 8; nt++) {
            const int n = nt*8 + g;
            unsigned int bh0 = __float_as_uint(sWh[n*68 + k0 + tg]);
            unsigned int bh1 = __float_as_uint(sWh[n*68 + k0 + tg + 4]);
            unsigned int bl0 = __float_as_uint(sWl[n*68 + k0 + tg]);
            unsigned int bl1 = __float_as_uint(sWl[n*68 + k0 + tg + 4]);
            mma_tf32(acc[nt], ah0, ah1, ah2, ah3, bh0, bh1);
            mma_tf32(acc[nt], ah0, ah1, ah2, ah3, bl0, bl1);
            mma_tf32(acc[nt], al0, al1, al2, al3, bh0, bh1);
        }
    }

    const size_t bh = (size_t)(b*HEADS_N + h);
    #pragma unroll
    for (int nt = 0; nt < 8; nt++) {
        const int col = nt*8 + 2*tg;
        *(float2*)&dst[(bh*TLEN + m0 + mr)*SDIM + col] =
            make_float2(acc[nt][0], acc[nt][1]);
        *(float2*)&dst[(bh*TLEN + m0 + mr + 8)*SDIM + col] =
            make_float2(acc[nt][2], acc[nt][3]);
    }
}

// ---------------- rel-pos GEMM v2: chunked, natural-layout B ----------------
__global__ void __launch_bounds__(256) relgemm_kernel(const float* __restrict__ Er) {
    extern __shared__ float sm[];
    const int tid = threadIdx.x;
    const int h = blockIdx.y, b = blockIdx.z;

    if (blockIdx.x == NCHUNK) {   // fused V-mean for (b,h)
        const int bh = b*HEADS_N + h;
        const int d = tid & 63, sub = tid >> 6;
        float a = 0.f;
        for (int l = sub; l < TLEN; l += 4)
            a += g_v[((size_t)bh*TLEN + l)*SDIM + d];
        sm[sub*64 + d] = a;
        __syncthreads();
        if (sub == 0)
            g_vmean[bh*SDIM + d] =
                (sm[d] + sm[64 + d] + sm[128 + d] + sm[192 + d]) * (1.f/(float)TLEN);
        return;
    }

    float* Qh = sm;              // [m=64][k] stride 68
    float* Ql = Qh + 64*68;
    float* Eh = Ql + 64*68;      // [n=o][k=s] natural rows, stride 68
    float* El = Eh + 64*68;

    const int x = (int)blockIdx.x;
    int it = 31, cb = 0;
    {
        int base = 0;
        for (int k = 0; k < 32; k++) {
            int nch = (k + 4) >> 2;
            if (x < base + nch) { it = k; cb = base; break; }
            base += nch;
        }
    }
    const int chunk = x - cb;
    const int osta = chunk*4;
    const int oend = min(osta + 4, it + 1);
    const int i0 = it * 64;

    const float* gq = g_q + (size_t)(b*HEADS_N + h)*TLEN*SDIM + (size_t)i0*SDIM;
    const float* ge = Er + (size_t)h*TLEN*SDIM;

    #pragma unroll
    for (int kk = 0; kk < 4; kk++) {
        int k = kk*256 + tid;
        int m = k >> 4, s4 = (k & 15)*4;
        float4 f = *(const float4*)&gq[m*SDIM + s4];
        float hx = tf32r(f.x), hy = tf32r(f.y), hz = tf32r(f.z), hw = tf32r(f.w);
        *(float4*)&Qh[m*68 + s4] = make_float4(hx, hy, hz, hw);
        *(float4*)&Ql[m*68 + s4] = make_float4(
            tf32r(f.x - hx), tf32r(f.y - hy), tf32r(f.z - hz), tf32r(f.w - hw));
    }

    const int w = tid >> 5, lane = tid & 31;
    const int g = lane >> 2, tg = lane & 3;
    const int mr = (w & 3)*16 + g;
    const int nb = (w >> 2)*32;

    const int W = 64*(it + 1);
    float* qb = g_qe + (size_t)(b*HEADS_N + h)*QE_BH + (size_t)4096*(it*(it + 1)/2);

    for (int oc = osta; oc < oend; oc++) {
        const int j0 = TLEN - 64 - i0 + oc*64;
        __syncthreads();
        #pragma unroll
        for (int kk = 0; kk < 4; kk++) {
            int k = kk*256 + tid;
            int o = k >> 4, s4 = (k & 15)*4;
            float4 f = *(const float4*)&ge[(size_t)(j0 + o)*SDIM + s4];
            float hx = tf32r(f.x), hy = tf32r(f.y), hz = tf32r(f.z), hw = tf32r(f.w);
            *(float4*)&Eh[o*68 + s4] = make_float4(hx, hy, hz, hw);
            *(float4*)&El[o*68 + s4] = make_float4(
                tf32r(f.x - hx), tf32r(f.y - hy), tf32r(f.z - hz), tf32r(f.w - hw));
        }
        __syncthreads();

        float d[4][4];
        #pragma unroll
        for (int nt = 0; nt < 4; nt++)
            #pragma unroll
            for (int i = 0; i < 4; i++) d[nt][i] = 0.f;

        #pragma unroll
        for (int kk = 0; kk < 8; kk++) {
            const int k0 = kk*8;
            unsigned int ah0 = __float_as_uint(Qh[mr*68 + k0 + tg]);
            unsigned int ah1 = __float_as_uint(Qh[(mr + 8)*68 + k0 + tg]);
            unsigned int ah2 = __float_as_uint(Qh[mr*68 + k0 + tg + 4]);
            unsigned int ah3 = __float_as_uint(Qh[(mr + 8)*68 + k0 + tg + 4]);
            unsigned int al0 = __float_as_uint(Ql[mr*68 + k0 + tg]);
            unsigned int al1 = __float_as_uint(Ql[(mr + 8)*68 + k0 + tg]);
            unsigned int al2 = __float_as_uint(Ql[mr*68 + k0 + tg + 4]);
            unsigned int al3 = __float_as_uint(Ql[(mr + 8)*68 + k0 + tg + 4]);
            #pragma unroll
            for (int nt = 0; nt < 4; nt++) {
                const int n = nb + nt*8 + g;
                unsigned int bh0 = __float_as_uint(Eh[n*68 + k0 + tg]);
                unsigned int bh1 = __float_as_uint(Eh[n*68 + k0 + tg + 4]);
                unsigned int bl0 = __float_as_uint(El[n*68 + k0 + tg]);
                unsigned int bl1 = __float_as_uint(El[n*68 + k0 + tg + 4]);
                mma_tf32(d[nt], ah0, ah1, ah2, ah3, bh0, bh1);
                mma_tf32(d[nt], ah0, ah1, ah2, ah3, bl0, bl1);
                mma_tf32(d[nt], al0, al1, al2, al3, bh0, bh1);
            }
        }

        const int colb = oc*64 + nb;
        #pragma unroll
        for (int nt = 0; nt < 4; nt++) {
            const int col = colb + nt*8 + 2*tg;
            *(float2*)&qb[(size_t)mr*W + col]       = make_float2(d[nt][0], d[nt][1]);
            *(float2*)&qb[(size_t)(mr + 8)*W + col] = make_float2(d[nt][2], d[nt][3]);
        }
    }
}

// ---------------- split-KV tensor-core flash attention (partials) ---------------
// 256 threads = 8 warps; warp (wr=w&3, wn=w>>2) owns 16 rows x 32 cols of the
// 64x64 S tile. Cross-warp softmax via smem exchange. K/V staged tf32-rounded;
// QK = (Qhi+Qlo)*Khi, PV = (Phi+Plo)*Vhi (identical numerics to previous round).
#define AST 68   // 68 mod 32 == 4 -> all fragment LDS conflict-free
__global__ void __launch_bounds__(256, 3) attn_part_kernel() {
    extern __shared__ float sm[];
    float* sQ = sm;              // [i][s]  64 x AST  fp32
    float* sK = sQ + 64*AST;     // [c][s]  tf32-hi (pre-scaled)
    float* sV = sK + 64*AST;     // [lc][d] tf32-hi
    float* sP = sV + 64*AST;     // [i][lc] fp32
    float* sredM = sP + 64*AST;  // [2][64] cross-warp max exchange
    float* sredS = sredM + 128;  // [2][64] cross-warp sum exchange

    const int x = NCHUNK - 1 - (int)blockIdx.x;   // heavy i-tiles first
    int it = 31, cb = 0;
    {
        int base = 0;
        for (int k = 0; k < 32; k++) {
            int nch = (k + 4) >> 2;
            if (x < base + nch) { it = k; cb = base; break; }
            base += nch;
        }
    }
    const int chunk = x - cb;
    const int csta = chunk*4;
    const int cend = min(csta + 4, it + 1);
    const int i0 = it * 64;

    const int h  = blockIdx.y;
    const int b  = blockIdx.z;
    const int tid = threadIdx.x;
    const int w = tid >> 5, lane = tid & 31;
    const int g = lane >> 2, tg = lane & 3;
    const int wr = w & 3, wn = w >> 2;
    const int rA = wr*16 + g, rB = rA + 8;
    const int nbase = wn*32;
    const float scale2 = 0.04419417382415922f;   // 512^-0.5

    const size_t bh = (size_t)(b*HEADS_N + h);
    const float* gq = g_q + bh*TLEN*SDIM;
    const float* gk = g_k + bh*TLEN*SDIM;
    const float* gv = g_v + bh*TLEN*SDIM;

    const int Wqe = 64*(it + 1);
    const float* qeb = g_qe + bh*QE_BH + (size_t)4096*(it*(it + 1)/2);
    const int omax = i0 + 63;

    for (int k = tid; k < 1024; k += 256) {
        int li = k >> 4, s4 = (k & 15)*4;
        *(float4*)&sQ[li*AST + s4] =
            *(const float4*)&gq[(size_t)(i0 + li)*SDIM + s4];
    }

    float mA = -1e30f, mB = -1e30f, lA = 0.f, lB = 0.f;
    float O[4][4];
    #pragma unroll
    for (int nt = 0; nt < 4; nt++)
        #pragma unroll
        for (int i = 0; i < 4; i++) O[nt][i] = 0.f;

    for (int ct = csta; ct < cend; ct++) {
        const int c0 = ct * 64;
        __syncthreads();
        for (int k = tid; k < 1024; k += 256) {
            int li = k >> 4, s4 = (k & 15)*4;
            float4 f = *(const float4*)&gk[(size_t)(c0 + li)*SDIM + s4];
            *(float4*)&sK[li*AST + s4] = make_float4(
                tf32r(f.x*scale2), tf32r(f.y*scale2),
                tf32r(f.z*scale2), tf32r(f.w*scale2));
            float4 v = *(const float4*)&gv[(size_t)(c0 + li)*SDIM + s4];
            *(float4*)&sV[li*AST + s4] = make_float4(
                tf32r(v.x), tf32r(v.y), tf32r(v.z), tf32r(v.w));
        }
        __syncthreads();

        float acc[4][4];
        #pragma unroll
        for (int nt = 0; nt < 4; nt++)
            #pragma unroll
            for (int i = 0; i < 4; i++) acc[nt][i] = 0.f;

        // ---- S = Q K^T : (Qhi + Qlo) * Khi ----
        #pragma unroll
        for (int kk = 0; kk < 8; kk++) {
            const int k0 = kk*8;
            float q0 = sQ[rA*AST + k0 + tg];
            float q1 = sQ[rB*AST + k0 + tg];
            float q2 = sQ[rA*AST + k0 + tg + 4];
            float q3 = sQ[rB*AST + k0 + tg + 4];
            unsigned int ah0 = f2tf32(q0), ah1 = f2tf32(q1);
            unsigned int ah2 = f2tf32(q2), ah3 = f2tf32(q3);
            unsigned int al0 = f2tf32(q0 - __uint_as_float(ah0));
            unsigned int al1 = f2tf32(q1 - __uint_as_float(ah1));
            unsigned int al2 = f2tf32(q2 - __uint_as_float(ah2));
            unsigned int al3 = f2tf32(q3 - __uint_as_float(ah3));
            #pragma unroll
            for (int nt = 0; nt < 4; nt++) {
                const int n = nbase + nt*8 + g;
                unsigned int bh0 = __float_as_uint(sK[n*AST + k0 + tg]);
                unsigned int bh1 = __float_as_uint(sK[n*AST + k0 + tg + 4]);
                mma_tf32(acc[nt], ah0, ah1, ah2, ah3, bh0, bh1);
                mma_tf32(acc[nt], al0, al1, al2, al3, bh0, bh1);
            }
        }

        // ---- rel-pos band + causal mask ----
        #pragma unroll
        for (int nt = 0; nt < 4; nt++) {
            const int cl = nbase + nt*8 + 2*tg;
            const int oA = 63 - rA + c0 + cl;
            const int oB = 63 - rB + c0 + cl;
            if (oA     <= omax) acc[nt][0] += __ldg(qeb + (size_t)rA*Wqe + oA);
            if (oA + 1 <= omax) acc[nt][1] += __ldg(qeb + (size_t)rA*Wqe + oA + 1);
            if (oB     <= omax) acc[nt][2] += __ldg(qeb + (size_t)rB*Wqe + oB);
            if (oB + 1 <= omax) acc[nt][3] += __ldg(qeb + (size_t)rB*Wqe + oB + 1);
            if (ct == it) {
                if (cl     > rA) acc[nt][0] = -1e30f;
                if (cl + 1 > rA) acc[nt][1] = -1e30f;
                if (cl     > rB) acc[nt][2] = -1e30f;
                if (cl + 1 > rB) acc[nt][3] = -1e30f;
            }
        }

        // ---- cross-warp online softmax ----
        float mxA = -1e30f, mxB = -1e30f;
        #pragma unroll
        for (int nt = 0; nt < 4; nt++) {
            mxA = fmaxf(mxA, fmaxf(acc[nt][0], acc[nt][1]));
            mxB = fmaxf(mxB, fmaxf(acc[nt][2], acc[nt][3]));
        }
        mxA = fmaxf(mxA, __shfl_xor_sync(0xffffffffu, mxA, 1));
        mxA = fmaxf(mxA, __shfl_xor_sync(0xffffffffu, mxA, 2));
        mxB = fmaxf(mxB, __shfl_xor_sync(0xffffffffu, mxB, 1));
        mxB = fmaxf(mxB, __shfl_xor_sync(0xffffffffu, mxB, 2));
        if (tg == 0) {
            sredM[wn*64 + rA] = mxA;
            sredM[wn*64 + rB] = mxB;
        }
        __syncthreads();
        mxA = fmaxf(mxA, sredM[(wn ^ 1)*64 + rA]);
        mxB = fmaxf(mxB, sredM[(wn ^ 1)*64 + rB]);

        const float mnA = fmaxf(mA, mxA), mnB = fmaxf(mB, mxB);
        const float cA = __expf(mA - mnA), cB = __expf(mB - mnB);
        float sA = 0.f, sB = 0.f;
        #pragma unroll
        for (int nt = 0; nt < 4; nt++) {
            acc[nt][0] = __expf(acc[nt][0] - mnA);
            acc[nt][1] = __expf(acc[nt][1] - mnA);
            acc[nt][2] = __expf(acc[nt][2] - mnB);
            acc[nt][3] = __expf(acc[nt][3] - mnB);
            sA += acc[nt][0] + acc[nt][1];
            sB += acc[nt][2] + acc[nt][3];
        }
        sA += __shfl_xor_sync(0xffffffffu, sA, 1);
        sA += __shfl_xor_sync(0xffffffffu, sA, 2);
        sB += __shfl_xor_sync(0xffffffffu, sB, 1);
        sB += __shfl_xor_sync(0xffffffffu, sB, 2);
        if (tg == 0) {
            sredS[wn*64 + rA] = sA;
            sredS[wn*64 + rB] = sB;
        }
        // stage this warp's P quarter while the sums propagate
        #pragma unroll
        for (int nt = 0; nt < 4; nt++) {
            *(float2*)&sP[rA*AST + nbase + nt*8 + 2*tg] =
                make_float2(acc[nt][0], acc[nt][1]);
            *(float2*)&sP[rB*AST + nbase + nt*8 + 2*tg] =
                make_float2(acc[nt][2], acc[nt][3]);
        }
        __syncthreads();   // sums visible AND full P tile complete
        sA += sredS[(wn ^ 1)*64 + rA];
        sB += sredS[(wn ^ 1)*64 + rB];

        lA = lA*cA + sA;  mA = mnA;
        lB = lB*cB + sB;  mB = mnB;
        #pragma unroll
        for (int nt = 0; nt < 4; nt++) {
            O[nt][0] *= cA; O[nt][1] *= cA;
            O[nt][2] *= cB; O[nt][3] *= cB;
        }

        // ---- O += P V : (Phi + Plo) * Vhi ----
        #pragma unroll
        for (int kk = 0; kk < 8; kk++) {
            const int k0 = kk*8;
            float p0 = sP[rA*AST + k0 + tg];
            float p1 = sP[rB*AST + k0 + tg];
            float p2 = sP[rA*AST + k0 + tg + 4];
            float p3 = sP[rB*AST + k0 + tg + 4];
            unsigned int ah0 = f2tf32(p0), ah1 = f2tf32(p1);
            unsigned int ah2 = f2tf32(p2), ah3 = f2tf32(p3);
            unsigned int al0 = f2tf32(p0 - __uint_as_float(ah0));
            unsigned int al1 = f2tf32(p1 - __uint_as_float(ah1));
            unsigned int al2 = f2tf32(p2 - __uint_as_float(ah2));
            unsigned int al3 = f2tf32(p3 - __uint_as_float(ah3));
            #pragma unroll
            for (int nt = 0; nt < 4; nt++) {
                const int n = nbase + nt*8 + g;
                unsigned int bh0 = __float_as_uint(sV[(k0 + tg)*AST + n]);
                unsigned int bh1 = __float_as_uint(sV[(k0 + tg + 4)*AST + n]);
                mma_tf32(O[nt], ah0, ah1, ah2, ah3, bh0, bh1);
                mma_tf32(O[nt], al0, al1, al2, al3, bh0, bh1);
            }
        }
    }

    const int slot = (int)(bh*NCHUNK) + cb + chunk;
    float* pO = g_pO + (size_t)slot*64*64;
    #pragma unroll
    for (int nt = 0; nt < 4; nt++) {
        const int col = nbase + nt*8 + 2*tg;
        *(float2*)&pO[rA*64 + col] = make_float2(O[nt][0], O[nt][1]);
        *(float2*)&pO[rB*64 + col] = make_float2(O[nt][2], O[nt][3]);
    }
    if (wn == 0 && tg == 0) {
        g_pm[slot*64 + rA] = mA;  g_pl[slot*64 + rA] = lA;
        g_pm[slot*64 + rB] = mB;  g_pl[slot*64 + rB] = lB;
    }
}

// ---------------- split-KV reduce: merge partials, mask, scramble --------------
__global__ void __launch_bounds__(128) reduce_kernel() {
    const int it = blockIdx.x, h = blockIdx.y, b = blockIdx.z;
    int base = 0;
    for (int k = 0; k < it; k++) base += (k + 4) >> 2;
    const int nc = (it + 4) >> 2;
    const int slot0 = (b*HEADS_N + h)*NCHUNK + base;
    const int tid = threadIdx.x;
    const int row = tid >> 1;
    const int half = (tid & 1)*32;

    float mstar = -1e30f;
    for (int p = 0; p < nc; p++)
        mstar = fmaxf(mstar, g_pm[(slot0 + p)*64 + row]);

    float lstar = 0.f;
    float Oa[32];
    #pragma unroll
    for (int d = 0; d < 32; d++) Oa[d] = 0.f;

    for (int p = 0; p < nc; p++) {
        const float f = __expf(g_pm[(slot0 + p)*64 + row] - mstar);
        lstar += g_pl[(slot0 + p)*64 + row] * f;
        const float* po = g_pO + ((size_t)(slot0 + p)*64 + row)*64 + half;
        #pragma unroll
        for (int d4 = 0; d4 < 8; d4++) {
            float4 v = *(const float4*)&po[d4*4];
            Oa[d4*4 + 0] += f*v.x;
            Oa[d4*4 + 1] += f*v.y;
            Oa[d4*4 + 2] += f*v.z;
            Oa[d4*4 + 3] += f*v.w;
        }
    }

    const int i = it*64 + row;
    const unsigned int mk = g_pmask[b*TLEN + i];
    const float inv = 1.f / lstar;
    float* dst = &g_attn[((size_t)(b*TLEN) + h*256 + (i >> 3))*EDIM
                         + ((i & 7) << 6) + half];
    if (mk != 0u) {
        #pragma unroll
        for (int d = 0; d < 32; d++) dst[d] = Oa[d]*inv;
    } else {
        const float* vm = &g_vmean[(b*HEADS_N + h)*SDIM + half];
        #pragma unroll
        for (int d = 0; d < 32; d++) dst[d] = vm[d];
    }
}

// ---------------- output projection via tf32 3x mma ----------------------------
__global__ void __launch_bounds__(256) outproj_kernel(const float* __restrict__ Wo,
                                                      const float* __restrict__ bo,
                                                      float* __restrict__ out) {
    extern __shared__ float sm[];
    float* sA  = sm;             // [row=128][k=64] fp32, stride 68
    float* sBh = sA + 128*68;    // [n=64][k] hi
    float* sBl = sBh + 64*68;    // lo

    const int m0 = blockIdx.x * 128;
    const int n0 = blockIdx.y * 64;
    const int tid = threadIdx.x;
    const int w = tid >> 5, lane = tid & 31;
    const int g = lane >> 2, tg = lane & 3;
    const int mr = w*16 + g;

    float acc[8][4];
    #pragma unroll
    for (int nt = 0; nt < 8; nt++)
        #pragma unroll
        for (int i = 0; i < 4; i++) acc[nt][i] = 0.f;

    for (int ks = 0; ks < 8; ks++) {
        const int kc = ks*64;
        __syncthreads();
        for (int k = tid; k < 2048; k += 256) {
            int row = k >> 4, i4 = (k & 15)*4;
            *(float4*)&sA[row*68 + i4] =
                *(const float4*)&g_attn[(size_t)(m0 + row)*EDIM + kc + i4];
        }
        for (int k = tid; k < 1024; k += 256) {
            int row = k >> 4, i4 = (k & 15)*4;
            float4 f = *(const float4*)&Wo[(size_t)(n0 + row)*EDIM + kc + i4];
            float hx = tf32r(f.x), hy = tf32r(f.y), hz = tf32r(f.z), hw = tf32r(f.w);
            *(float4*)&sBh[row*68 + i4] = make_float4(hx, hy, hz, hw);
            *(float4*)&sBl[row*68 + i4] = make_float4(
                tf32r(f.x - hx), tf32r(f.y - hy), tf32r(f.z - hz), tf32r(f.w - hw));
        }
        __syncthreads();

        #pragma unroll
        for (int kk = 0; kk < 8; kk++) {
            const int k0 = kk*8;
            float q0 = sA[mr*68 + k0 + tg];
            float q1 = sA[(mr + 8)*68 + k0 + tg];
            float q2 = sA[mr*68 + k0 + tg + 4];
            float q3 = sA[(mr + 8)*68 + k0 + tg + 4];
            unsigned int ah0 = f2tf32(q0), ah1 = f2tf32(q1);
            unsigned int ah2 = f2tf32(q2), ah3 = f2tf32(q3);
            unsigned int al0 = f2tf32(q0 - __uint_as_float(ah0));
            unsigned int al1 = f2tf32(q1 - __uint_as_float(ah1));
            unsigned int al2 = f2tf32(q2 - __uint_as_float(ah2));
            unsigned int al3 = f2tf32(q3 - __uint_as_float(ah3));
            #pragma unroll
            for (int nt = 0; nt < 8; nt++) {
                const int n = nt*8 + g;
                unsigned int bh0 = __float_as_uint(sBh[n*68 + k0 + tg]);
                unsigned int bh1 = __float_as_uint(sBh[n*68 + k0 + tg + 4]);
                unsigned int bl0 = __float_as_uint(sBl[n*68 + k0 + tg]);
                unsigned int bl1 = __float_as_uint(sBl[n*68 + k0 + tg + 4]);
                mma_tf32(acc[nt], ah0, ah1, ah2, ah3, bh0, bh1);
                mma_tf32(acc[nt], ah0, ah1, ah2, ah3, bl0, bl1);
                mma_tf32(acc[nt], al0, al1, al2, al3, bh0, bh1);
            }
        }
    }

    #pragma unroll
    for (int nt = 0; nt < 8; nt++) {
        const int col = n0 + nt*8 + 2*tg;
        const float b0v = bo[col], b1v = bo[col + 1];
        *(float2*)&out[(size_t)(m0 + mr)*EDIM + col] =
            make_float2(acc[nt][0] + b0v, acc[nt][1] + b1v);
        *(float2*)&out[(size_t)(m0 + mr + 8)*EDIM + col] =
            make_float2(acc[nt][2] + b0v, acc[nt][3] + b1v);
    }
}

// ---------------- launch ----------------
extern "C" void kernel_launch(void* const* d_in, const int* in_sizes, int n_in,
                              void* d_out, int out_size) {
    int idx_x = -1, idx_Er = -1, idx_Wo = -1, idx_bo = -1;
    int cand[8]; int ncand = 0;
    for (int scale = 1; scale <= 4; scale *= 4) {
        idx_x = idx_Er = idx_Wo = idx_bo = -1; ncand = 0;
        for (int i = 0; i < n_in; i++) {
            long long s = in_sizes[i];
            if      (s == (long long)BATCH*TLEN*EDIM*scale)   idx_x  = i;
            else if (s == (long long)HEADS_N*TLEN*SDIM*scale) idx_Er = i;
            else if (s == (long long)EDIM*EDIM*scale)         idx_Wo = i;
            else if (s == (long long)EDIM*scale)              idx_bo = i;
            else if (s == (long long)SDIM*SDIM*scale && ncand < 8) cand[ncand++] = i;
        }
        if (idx_x >= 0 && idx_Er >= 0 && idx_Wo >= 0 && idx_bo >= 0 && ncand == 4)
            break;
    }
    if (!(idx_x >= 0 && idx_Er >= 0 && idx_Wo >= 0 && idx_bo >= 0 && ncand == 4)) {
        int wi = (n_in >= 9) ? 3 : 2;
        idx_x = 0; cand[0] = 1; cand[1] = wi; cand[2] = wi + 1; cand[3] = wi + 2;
        idx_Er = wi + 3; idx_Wo = wi + 4; idx_bo = wi + 5; ncand = 4;
    }

    const float* x  = (const float*)d_in[idx_x];
    const float* Er = (const float*)d_in[idx_Er];
    const float* Wo = (const float*)d_in[idx_Wo];
    const float* bo = (const float*)d_in[idx_bo];
    float* out = (float*)d_out;

    const int PROJ_SMEM = (256*68) * (int)sizeof(float);            // 69632 B
    const int ATTN_SMEM = (4*64*AST + 256) * (int)sizeof(float);    // 70656 B
    const int RG_SMEM   = (4*64*68) * (int)sizeof(float);           // 69632 B
    const int OP_SMEM   = (256*68) * (int)sizeof(float);            // 69632 B
    cudaFuncSetAttribute(proj_kernel, cudaFuncAttributeMaxDynamicSharedMemorySize, PROJ_SMEM);
    cudaFuncSetAttribute(attn_part_kernel, cudaFuncAttributeMaxDynamicSharedMemorySize, ATTN_SMEM);
    cudaFuncSetAttribute(relgemm_kernel, cudaFuncAttributeMaxDynamicSharedMemorySize, RG_SMEM);
    cudaFuncSetAttribute(outproj_kernel, cudaFuncAttributeMaxDynamicSharedMemorySize, OP_SMEM);

    select_inputs<<<1, 256>>>((const float*)d_in[cand[0]], (const float*)d_in[cand[1]],
                              (const float*)d_in[cand[2]], (const float*)d_in[cand[3]],
                              (idx_x == 0) ? 1 : 0);
    proj_kernel<<<dim3(TLEN/128, 3*HEADS_N, BATCH), 256, PROJ_SMEM>>>(x);
    relgemm_kernel<<<dim3(NCHUNK + 1, HEADS_N, BATCH), 256, RG_SMEM>>>(Er);
    attn_part_kernel<<<dim3(NCHUNK, HEADS_N, BATCH), 256, ATTN_SMEM>>>();
    reduce_kernel<<<dim3(TLEN/64, HEADS_N, BATCH), 128>>>();
    outproj_kernel<<<dim3((BATCH*TLEN)/128, EDIM/64), 256, OP_SMEM>>>(Wo, bo, out);
}

// round 16
// speedup vs baseline: 1.1000x; 1.1000x over previous
#include <cuda_runtime.h>
#include <math.h>

#define TLEN    2048
#define HEADS_N 8
#define BATCH   2
#define SDIM    64
#define EDIM    512
#define QE_BH   2162688   // 4096 * 528 floats per (b,h)
#define NCHUNK  144       // sum over it of ceil((it+1)/4)

// ---------------- scratch + resolved input pointers (device-resident) ----------
__device__ float g_q[BATCH*HEADS_N*TLEN*SDIM];
__device__ float g_k[BATCH*HEADS_N*TLEN*SDIM];   // tf32-rounded, pre-scaled 512^-0.5
__device__ float g_v[BATCH*HEADS_N*TLEN*SDIM];   // tf32-rounded
__device__ float g_vmean[BATCH*HEADS_N*SDIM];
__device__ float g_attn[BATCH*TLEN*EDIM];
__device__ float g_qe[BATCH*HEADS_N*QE_BH];   // triangular-packed QE bands
__device__ float g_pO[(size_t)BATCH*HEADS_N*NCHUNK*64*64];   // split-KV partials
__device__ float g_pm[BATCH*HEADS_N*NCHUNK*64];
__device__ float g_pl[BATCH*HEADS_N*NCHUNK*64];

__device__ const float*        g_pWq;
__device__ const float*        g_pWk;
__device__ const float*        g_pWv;
__device__ const unsigned int* g_pmask;

// ---------------- tf32 + cp.async helpers ----------------
__device__ __forceinline__ unsigned int f2tf32(float x) {
    unsigned int r;
    asm("cvt.rna.tf32.f32 %0, %1;" : "=r"(r) : "f"(x));
    return r;
}
__device__ __forceinline__ float tf32r(float x) {
    return __uint_as_float(f2tf32(x));
}
__device__ __forceinline__ void mma_tf32(float d[4],
        unsigned int a0, unsigned int a1, unsigned int a2, unsigned int a3,
        unsigned int b0, unsigned int b1) {
    asm("mma.sync.aligned.m16n8k8.row.col.f32.tf32.tf32.f32 "
        "{%0,%1,%2,%3}, {%4,%5,%6,%7}, {%8,%9}, {%0,%1,%2,%3};"
        : "+f"(d[0]), "+f"(d[1]), "+f"(d[2]), "+f"(d[3])
        : "r"(a0), "r"(a1), "r"(a2), "r"(a3), "r"(b0), "r"(b1));
}
__device__ __forceinline__ void cpa16(void* s, const void* g) {
    unsigned int sa = (unsigned int)__cvta_generic_to_shared(s);
    asm volatile("cp.async.cg.shared.global [%0], [%1], 16;" :: "r"(sa), "l"(g));
}
__device__ __forceinline__ void cpa_commit() {
    asm volatile("cp.async.commit_group;");
}
__device__ __forceinline__ void cpa_wait0() {
    asm volatile("cp.async.wait_group 0;");
}

// ---------------- prologue: content-based identification of mask ---------------
__global__ void select_inputs(const float* c0, const float* c1,
                              const float* c2, const float* c3, int x_first) {
    __shared__ int bad[4];
    const float* cand[4] = {c0, c1, c2, c3};
    if (threadIdx.x < 4) bad[threadIdx.x] = 0;
    __syncthreads();
    for (int j = 0; j < 4; j++) {
        const unsigned int* p = (const unsigned int*)cand[j];
        int b = 0;
        for (int i = threadIdx.x; i < 512; i += blockDim.x) {   // 512 words suffice
            unsigned int v = p[i];
            if (v != 0u && v != 1u && v != 0x3F800000u) { b = 1; break; }
        }
        if (b) atomicOr(&bad[j], 1);
    }
    __syncthreads();
    if (threadIdx.x == 0) {
        int mi = -1;
        for (int j = 0; j < 4; j++) if (!bad[j]) { mi = j; break; }
        if (mi < 0) mi = x_first ? 0 : 3;
        const float* rest[3]; int n = 0;
        for (int j = 0; j < 4; j++) if (j != mi) rest[n++] = cand[j];
        g_pmask = (const unsigned int*)cand[mi];
        if (x_first) { g_pWq = rest[0]; g_pWk = rest[1]; g_pWv = rest[2]; }
        else         { g_pWk = rest[0]; g_pWq = rest[1]; g_pWv = rest[2]; }
    }
}

// ---------------- QKV projection via tf32 3x mma ----------------
// K output: tf32r(k * 512^-0.5); V output: tf32r(v); Q output: fp32.
__global__ void __launch_bounds__(256) proj_kernel(const float* __restrict__ x) {
    extern __shared__ float sm[];
    float* sX = sm;              // [row=128][k=64] fp32, stride 68
    float* sWh = sX + 128*68;    // [o=64][k] hi
    float* sWl = sWh + 64*68;    // lo

    const int m0 = blockIdx.x * 128;
    const int h  = blockIdx.y / 3;
    const int mm = blockIdx.y % 3;
    const int b  = blockIdx.z;
    const int tid = threadIdx.x;
    const float* W = (mm == 0) ? g_pWq : (mm == 1) ? g_pWk : g_pWv;
    float* dst = (mm == 0) ? g_q : (mm == 1) ? g_k : g_v;

    for (int k = tid; k < 2048; k += 256) {
        int row = k >> 4, i4 = (k & 15)*4;
        cpa16(&sX[row*68 + i4],
              &x[(size_t)(b*TLEN + m0 + row)*EDIM + h*SDIM + i4]);
    }
    cpa_commit();
    for (int k = tid; k < 1024; k += 256) {
        int row = k >> 4, i4 = (k & 15)*4;
        float4 f = *(const float4*)&W[row*SDIM + i4];
        float hx = tf32r(f.x), hy = tf32r(f.y), hz = tf32r(f.z), hw = tf32r(f.w);
        *(float4*)&sWh[row*68 + i4] = make_float4(hx, hy, hz, hw);
        *(float4*)&sWl[row*68 + i4] = make_float4(
            tf32r(f.x - hx), tf32r(f.y - hy), tf32r(f.z - hz), tf32r(f.w - hw));
    }
    cpa_wait0();
    __syncthreads();

    const int w = tid >> 5, lane = tid & 31;
    const int g = lane >> 2, tg = lane & 3;
    const int mr = w*16 + g;

    float acc[8][4];
    #pragma unroll
    for (int nt = 0; nt < 8; nt++)
        #pragma unroll
        for (int i = 0; i < 4; i++) acc[nt][i] = 0.f;

    #pragma unroll
    for (int kk = 0; kk < 8; kk++) {
        const int k0 = kk*8;
        float q0 = sX[mr*68 + k0 + tg];
        float q1 = sX[(mr + 8)*68 + k0 + tg];
        float q2 = sX[mr*68 + k0 + tg + 4];
        float q3 = sX[(mr + 8)*68 + k0 + tg + 4];
        unsigned int ah0 = f2tf32(q0), ah1 = f2tf32(q1);
        unsigned int ah2 = f2tf32(q2), ah3 = f2tf32(q3);
        unsigned int al0 = f2tf32(q0 - __uint_as_float(ah0));
        unsigned int al1 = f2tf32(q1 - __uint_as_float(ah1));
        unsigned int al2 = f2tf32(q2 - __uint_as_float(ah2));
        unsigned int al3 = f2tf32(q3 - __uint_as_float(ah3));
        #pragma unroll
        for (int nt = 0; nt < 8; nt++) {
            const int n = nt*8 + g;
            unsigned int bh0 = __float_as_uint(sWh[n*68 + k0 + tg]);
            unsigned int bh1 = __float_as_uint(sWh[n*68 + k0 + tg + 4]);
            unsigned int bl0 = __float_as_uint(sWl[n*68 + k0 + tg]);
            unsigned int bl1 = __float_as_uint(sWl[n*68 + k0 + tg + 4]);
            mma_tf32(acc[nt], ah0, ah1, ah2, ah3, bh0, bh1);
            mma_tf32(acc[nt], ah0, ah1, ah2, ah3, bl0, bl1);
            mma_tf32(acc[nt], al0, al1, al2, al3, bh0, bh1);
        }
    }

    const float scale2 = 0.04419417382415922f;   // 512^-0.5
    const size_t bh = (size_t)(b*HEADS_N + h);
    #pragma unroll
    for (int nt = 0; nt < 8; nt++) {
        const int col = nt*8 + 2*tg;
        float v0 = acc[nt][0], v1 = acc[nt][1];
        float v2 = acc[nt][2], v3 = acc[nt][3];
        if (mm == 1) {
            v0 = tf32r(v0*scale2); v1 = tf32r(v1*scale2);
            v2 = tf32r(v2*scale2); v3 = tf32r(v3*scale2);
        } else if (mm == 2) {
            v0 = tf32r(v0); v1 = tf32r(v1);
            v2 = tf32r(v2); v3 = tf32r(v3);
        }
        *(float2*)&dst[(bh*TLEN + m0 + mr)*SDIM + col] = make_float2(v0, v1);
        *(float2*)&dst[(bh*TLEN + m0 + mr + 8)*SDIM + col] = make_float2(v2, v3);
    }
}

// ---------------- rel-pos GEMM v2: chunked, natural-layout B ----------------
__global__ void __launch_bounds__(256) relgemm_kernel(const float* __restrict__ Er) {
    extern __shared__ float sm[];
    const int tid = threadIdx.x;
    const int h = blockIdx.y, b = blockIdx.z;

    if (blockIdx.x == NCHUNK) {   // fused V-mean for (b,h)
        const int bh = b*HEADS_N + h;
        const int d = tid & 63, sub = tid >> 6;
        float a = 0.f;
        for (int l = sub; l < TLEN; l += 4)
            a += g_v[((size_t)bh*TLEN + l)*SDIM + d];
        sm[sub*64 + d] = a;
        __syncthreads();
        if (sub == 0)
            g_vmean[bh*SDIM + d] =
                (sm[d] + sm[64 + d] + sm[128 + d] + sm[192 + d]) * (1.f/(float)TLEN);
        return;
    }

    float* Qh = sm;              // [m=64][k] stride 68
    float* Ql = Qh + 64*68;
    float* Eh = Ql + 64*68;      // [n=o][k=s] natural rows, stride 68
    float* El = Eh + 64*68;

    const int x = (int)blockIdx.x;
    int it = 31, cb = 0;
    {
        int base = 0;
        for (int k = 0; k < 32; k++) {
            int nch = (k + 4) >> 2;
            if (x < base + nch) { it = k; cb = base; break; }
            base += nch;
        }
    }
    const int chunk = x - cb;
    const int osta = chunk*4;
    const int oend = min(osta + 4, it + 1);
    const int i0 = it * 64;

    const float* gq = g_q + (size_t)(b*HEADS_N + h)*TLEN*SDIM + (size_t)i0*SDIM;
    const float* ge = Er + (size_t)h*TLEN*SDIM;

    #pragma unroll
    for (int kk = 0; kk < 4; kk++) {
        int k = kk*256 + tid;
        int m = k >> 4, s4 = (k & 15)*4;
        float4 f = *(const float4*)&gq[m*SDIM + s4];
        float hx = tf32r(f.x), hy = tf32r(f.y), hz = tf32r(f.z), hw = tf32r(f.w);
        *(float4*)&Qh[m*68 + s4] = make_float4(hx, hy, hz, hw);
        *(float4*)&Ql[m*68 + s4] = make_float4(
            tf32r(f.x - hx), tf32r(f.y - hy), tf32r(f.z - hz), tf32r(f.w - hw));
    }

    const int w = tid >> 5, lane = tid & 31;
    const int g = lane >> 2, tg = lane & 3;
    const int mr = (w & 3)*16 + g;
    const int nb = (w >> 2)*32;

    const int W = 64*(it + 1);
    float* qb = g_qe + (size_t)(b*HEADS_N + h)*QE_BH + (size_t)4096*(it*(it + 1)/2);

    for (int oc = osta; oc < oend; oc++) {
        const int j0 = TLEN - 64 - i0 + oc*64;
        __syncthreads();
        #pragma unroll
        for (int kk = 0; kk < 4; kk++) {
            int k = kk*256 + tid;
            int o = k >> 4, s4 = (k & 15)*4;
            float4 f = *(const float4*)&ge[(size_t)(j0 + o)*SDIM + s4];
            float hx = tf32r(f.x), hy = tf32r(f.y), hz = tf32r(f.z), hw = tf32r(f.w);
            *(float4*)&Eh[o*68 + s4] = make_float4(hx, hy, hz, hw);
            *(float4*)&El[o*68 + s4] = make_float4(
                tf32r(f.x - hx), tf32r(f.y - hy), tf32r(f.z - hz), tf32r(f.w - hw));
        }
        __syncthreads();

        float d[4][4];
        #pragma unroll
        for (int nt = 0; nt < 4; nt++)
            #pragma unroll
            for (int i = 0; i < 4; i++) d[nt][i] = 0.f;

        #pragma unroll
        for (int kk = 0; kk < 8; kk++) {
            const int k0 = kk*8;
            unsigned int ah0 = __float_as_uint(Qh[mr*68 + k0 + tg]);
            unsigned int ah1 = __float_as_uint(Qh[(mr + 8)*68 + k0 + tg]);
            unsigned int ah2 = __float_as_uint(Qh[mr*68 + k0 + tg + 4]);
            unsigned int ah3 = __float_as_uint(Qh[(mr + 8)*68 + k0 + tg + 4]);
            unsigned int al0 = __float_as_uint(Ql[mr*68 + k0 + tg]);
            unsigned int al1 = __float_as_uint(Ql[(mr + 8)*68 + k0 + tg]);
            unsigned int al2 = __float_as_uint(Ql[mr*68 + k0 + tg + 4]);
            unsigned int al3 = __float_as_uint(Ql[(mr + 8)*68 + k0 + tg + 4]);
            #pragma unroll
            for (int nt = 0; nt < 4; nt++) {
                const int n = nb + nt*8 + g;
                unsigned int bh0 = __float_as_uint(Eh[n*68 + k0 + tg]);
                unsigned int bh1 = __float_as_uint(Eh[n*68 + k0 + tg + 4]);
                unsigned int bl0 = __float_as_uint(El[n*68 + k0 + tg]);
                unsigned int bl1 = __float_as_uint(El[n*68 + k0 + tg + 4]);
                mma_tf32(d[nt], ah0, ah1, ah2, ah3, bh0, bh1);
                mma_tf32(d[nt], ah0, ah1, ah2, ah3, bl0, bl1);
                mma_tf32(d[nt], al0, al1, al2, al3, bh0, bh1);
            }
        }

        const int colb = oc*64 + nb;
        #pragma unroll
        for (int nt = 0; nt < 4; nt++) {
            const int col = colb + nt*8 + 2*tg;
            *(float2*)&qb[(size_t)mr*W + col]       = make_float2(d[nt][0], d[nt][1]);
            *(float2*)&qb[(size_t)(mr + 8)*W + col] = make_float2(d[nt][2], d[nt][3]);
        }
    }
}

// ---------------- split-KV tensor-core flash attention (partials) ---------------
// 128 threads = 4 warps (R14 layout). K,V arrive PRE-ROUNDED (K pre-scaled) from
// proj, so staging is pure cp.async 16B. QK = (Qhi+Qlo)*Khi, PV = (Phi+Plo)*Vhi.
#define AST 68   // 68 mod 32 == 4 -> all fragment LDS conflict-free
__global__ void __launch_bounds__(128, 3) attn_part_kernel() {
    extern __shared__ float sm[];
    float* sQ = sm;              // [i][s]  64 x AST  fp32
    float* sK = sQ + 64*AST;     // [c][s]  tf32-hi, pre-scaled
    float* sV = sK + 64*AST;     // [lc][d] tf32-hi
    float* sP = sV + 64*AST;     // [i][lc] fp32

    const int x = NCHUNK - 1 - (int)blockIdx.x;   // heavy i-tiles first
    int it = 31, cb = 0;
    {
        int base = 0;
        for (int k = 0; k < 32; k++) {
            int nch = (k + 4) >> 2;
            if (x < base + nch) { it = k; cb = base; break; }
            base += nch;
        }
    }
    const int chunk = x - cb;
    const int csta = chunk*4;
    const int cend = min(csta + 4, it + 1);
    const int i0 = it * 64;

    const int h  = blockIdx.y;
    const int b  = blockIdx.z;
    const int tid = threadIdx.x;
    const int w = tid >> 5, lane = tid & 31;
    const int g = lane >> 2, tg = lane & 3;
    const int rA = w*16 + g, rB = rA + 8;

    const size_t bh = (size_t)(b*HEADS_N + h);
    const float* gq = g_q + bh*TLEN*SDIM;
    const float* gk = g_k + bh*TLEN*SDIM;
    const float* gv = g_v + bh*TLEN*SDIM;

    const int Wqe = 64*(it + 1);
    const float* qeb = g_qe + bh*QE_BH + (size_t)4096*(it*(it + 1)/2);
    const int omax = i0 + 63;

    // stage Q via cp.async (fp32, unscaled — scale lives in g_k)
    for (int k = tid; k < 1024; k += 128) {
        int li = k >> 4, s4 = (k & 15)*4;
        cpa16(&sQ[li*AST + s4], &gq[(size_t)(i0 + li)*SDIM + s4]);
    }
    cpa_commit();

    float mA = -1e30f, mB = -1e30f, lA = 0.f, lB = 0.f;
    float O[8][4];
    #pragma unroll
    for (int nt = 0; nt < 8; nt++)
        #pragma unroll
        for (int i = 0; i < 4; i++) O[nt][i] = 0.f;

    for (int ct = csta; ct < cend; ct++) {
        const int c0 = ct * 64;
        __syncthreads();   // prev tile fully consumed
        for (int k = tid; k < 1024; k += 128) {
            int li = k >> 4, s4 = (k & 15)*4;
            cpa16(&sK[li*AST + s4], &gk[(size_t)(c0 + li)*SDIM + s4]);
            cpa16(&sV[li*AST + s4], &gv[(size_t)(c0 + li)*SDIM + s4]);
        }
        cpa_commit();
        cpa_wait0();       // also covers the Q group on first iteration
        __syncthreads();

        float acc[8][4];
        #pragma unroll
        for (int nt = 0; nt < 8; nt++)
            #pragma unroll
            for (int i = 0; i < 4; i++) acc[nt][i] = 0.f;

        // ---- S = Q K^T : (Qhi + Qlo) * Khi ----
        #pragma unroll
        for (int kk = 0; kk < 8; kk++) {
            const int k0 = kk*8;
            float q0 = sQ[rA*AST + k0 + tg];
            float q1 = sQ[rB*AST + k0 + tg];
            float q2 = sQ[rA*AST + k0 + tg + 4];
            float q3 = sQ[rB*AST + k0 + tg + 4];
            unsigned int ah0 = f2tf32(q0), ah1 = f2tf32(q1);
            unsigned int ah2 = f2tf32(q2), ah3 = f2tf32(q3);
            unsigned int al0 = f2tf32(q0 - __uint_as_float(ah0));
            unsigned int al1 = f2tf32(q1 - __uint_as_float(ah1));
            unsigned int al2 = f2tf32(q2 - __uint_as_float(ah2));
            unsigned int al3 = f2tf32(q3 - __uint_as_float(ah3));
            #pragma unroll
            for (int nt = 0; nt < 8; nt++) {
                const int n = nt*8 + g;
                unsigned int bh0 = __float_as_uint(sK[n*AST + k0 + tg]);
                unsigned int bh1 = __float_as_uint(sK[n*AST + k0 + tg + 4]);
                mma_tf32(acc[nt], ah0, ah1, ah2, ah3, bh0, bh1);
                mma_tf32(acc[nt], al0, al1, al2, al3, bh0, bh1);
            }
        }

        #pragma unroll
        for (int nt = 0; nt < 8; nt++) {
            const int cl = nt*8 + 2*tg;
            const int oA = 63 - rA + c0 + cl;
            const int oB = 63 - rB + c0 + cl;
            if (oA     <= omax) acc[nt][0] += __ldg(qeb + (size_t)rA*Wqe + oA);
            if (oA + 1 <= omax) acc[nt][1] += __ldg(qeb + (size_t)rA*Wqe + oA + 1);
            if (oB     <= omax) acc[nt][2] += __ldg(qeb + (size_t)rB*Wqe + oB);
            if (oB + 1 <= omax) acc[nt][3] += __ldg(qeb + (size_t)rB*Wqe + oB + 1);
            if (ct == it) {
                if (cl     > rA) acc[nt][0] = -1e30f;
                if (cl + 1 > rA) acc[nt][1] = -1e30f;
                if (cl     > rB) acc[nt][2] = -1e30f;
                if (cl + 1 > rB) acc[nt][3] = -1e30f;
            }
        }

        float mxA = -1e30f, mxB = -1e30f;
        #pragma unroll
        for (int nt = 0; nt < 8; nt++) {
            mxA = fmaxf(mxA, fmaxf(acc[nt][0], acc[nt][1]));
            mxB = fmaxf(mxB, fmaxf(acc[nt][2], acc[nt][3]));
        }
        mxA = fmaxf(mxA, __shfl_xor_sync(0xffffffffu, mxA, 1));
        mxA = fmaxf(mxA, __shfl_xor_sync(0xffffffffu, mxA, 2));
        mxB = fmaxf(mxB, __shfl_xor_sync(0xffffffffu, mxB, 1));
        mxB = fmaxf(mxB, __shfl_xor_sync(0xffffffffu, mxB, 2));
        const float mnA = fmaxf(mA, mxA), mnB = fmaxf(mB, mxB);
        const float cA = __expf(mA - mnA), cB = __expf(mB - mnB);
        float sA = 0.f, sB = 0.f;
        #pragma unroll
        for (int nt = 0; nt < 8; nt++) {
            acc[nt][0] = __expf(acc[nt][0] - mnA);
            acc[nt][1] = __expf(acc[nt][1] - mnA);
            acc[nt][2] = __expf(acc[nt][2] - mnB);
            acc[nt][3] = __expf(acc[nt][3] - mnB);
            sA += acc[nt][0] + acc[nt][1];
            sB += acc[nt][2] + acc[nt][3];
        }
        sA += __shfl_xor_sync(0xffffffffu, sA, 1);
        sA += __shfl_xor_sync(0xffffffffu, sA, 2);
        sB += __shfl_xor_sync(0xffffffffu, sB, 1);
        sB += __shfl_xor_sync(0xffffffffu, sB, 2);
        lA = lA*cA + sA;  mA = mnA;
        lB = lB*cB + sB;  mB = mnB;
        #pragma unroll
        for (int nt = 0; nt < 8; nt++) {
            O[nt][0] *= cA; O[nt][1] *= cA;
            O[nt][2] *= cB; O[nt][3] *= cB;
        }

        #pragma unroll
        for (int nt = 0; nt < 8; nt++) {
            *(float2*)&sP[rA*AST + nt*8 + 2*tg] = make_float2(acc[nt][0], acc[nt][1]);
            *(float2*)&sP[rB*AST + nt*8 + 2*tg] = make_float2(acc[nt][2], acc[nt][3]);
        }
        __syncwarp();

        // ---- O += P V : (Phi + Plo) * Vhi ----
        #pragma unroll
        for (int kk = 0; kk < 8; kk++) {
            const int k0 = kk*8;
            float p0 = sP[rA*AST + k0 + tg];
            float p1 = sP[rB*AST + k0 + tg];
            float p2 = sP[rA*AST + k0 + tg + 4];
            float p3 = sP[rB*AST + k0 + tg + 4];
            unsigned int ah0 = f2tf32(p0), ah1 = f2tf32(p1);
            unsigned int ah2 = f2tf32(p2), ah3 = f2tf32(p3);
            unsigned int al0 = f2tf32(p0 - __uint_as_float(ah0));
            unsigned int al1 = f2tf32(p1 - __uint_as_float(ah1));
            unsigned int al2 = f2tf32(p2 - __uint_as_float(ah2));
            unsigned int al3 = f2tf32(p3 - __uint_as_float(ah3));
            #pragma unroll
            for (int nt = 0; nt < 8; nt++) {
                const int n = nt*8 + g;
                unsigned int bh0 = __float_as_uint(sV[(k0 + tg)*AST + n]);
                unsigned int bh1 = __float_as_uint(sV[(k0 + tg + 4)*AST + n]);
                mma_tf32(O[nt], ah0, ah1, ah2, ah3, bh0, bh1);
                mma_tf32(O[nt], al0, al1, al2, al3, bh0, bh1);
            }
        }
    }

    const int slot = (int)(bh*NCHUNK) + cb + chunk;
    float* pO = g_pO + (size_t)slot*64*64;
    #pragma unroll
    for (int nt = 0; nt < 8; nt++) {
        *(float2*)&pO[rA*64 + nt*8 + 2*tg] = make_float2(O[nt][0], O[nt][1]);
        *(float2*)&pO[rB*64 + nt*8 + 2*tg] = make_float2(O[nt][2], O[nt][3]);
    }
    if (tg == 0) {
        g_pm[slot*64 + rA] = mA;  g_pl[slot*64 + rA] = lA;
        g_pm[slot*64 + rB] = mB;  g_pl[slot*64 + rB] = lB;
    }
}

// ---------------- split-KV reduce: merge partials, mask, scramble --------------
__global__ void __launch_bounds__(128) reduce_kernel() {
    const int it = blockIdx.x, h = blockIdx.y, b = blockIdx.z;
    int base = 0;
    for (int k = 0; k < it; k++) base += (k + 4) >> 2;
    const int nc = (it + 4) >> 2;
    const int slot0 = (b*HEADS_N + h)*NCHUNK + base;
    const int tid = threadIdx.x;
    const int row = tid >> 1;
    const int half = (tid & 1)*32;

    float mstar = -1e30f;
    for (int p = 0; p < nc; p++)
        mstar = fmaxf(mstar, g_pm[(slot0 + p)*64 + row]);

    float lstar = 0.f;
    float Oa[32];
    #pragma unroll
    for (int d = 0; d < 32; d++) Oa[d] = 0.f;

    for (int p = 0; p < nc; p++) {
        const float f = __expf(g_pm[(slot0 + p)*64 + row] - mstar);
        lstar += g_pl[(slot0 + p)*64 + row] * f;
        const float* po = g_pO + ((size_t)(slot0 + p)*64 + row)*64 + half;
        #pragma unroll
        for (int d4 = 0; d4 < 8; d4++) {
            float4 v = *(const float4*)&po[d4*4];
            Oa[d4*4 + 0] += f*v.x;
            Oa[d4*4 + 1] += f*v.y;
            Oa[d4*4 + 2] += f*v.z;
            Oa[d4*4 + 3] += f*v.w;
        }
    }

    const int i = it*64 + row;
    const unsigned int mk = g_pmask[b*TLEN + i];
    const float inv = 1.f / lstar;
    float* dst = &g_attn[((size_t)(b*TLEN) + h*256 + (i >> 3))*EDIM
                         + ((i & 7) << 6) + half];
    if (mk != 0u) {
        #pragma unroll
        for (int d = 0; d < 32; d++) dst[d] = Oa[d]*inv;
    } else {
        const float* vm = &g_vmean[(b*HEADS_N + h)*SDIM + half];
        #pragma unroll
        for (int d = 0; d < 32; d++) dst[d] = vm[d];
    }
}

// ---------------- output projection via tf32 3x mma ----------------------------
__global__ void __launch_bounds__(256) outproj_kernel(const float* __restrict__ Wo,
                                                      const float* __restrict__ bo,
                                                      float* __restrict__ out) {
    extern __shared__ float sm[];
    float* sA  = sm;             // [row=128][k=64] fp32, stride 68
    float* sBh = sA + 128*68;    // [n=64][k] hi
    float* sBl = sBh + 64*68;    // lo

    const int m0 = blockIdx.x * 128;
    const int n0 = blockIdx.y * 64;
    const int tid = threadIdx.x;
    const int w = tid >> 5, lane = tid & 31;
    const int g = lane >> 2, tg = lane & 3;
    const int mr = w*16 + g;

    float acc[8][4];
    #pragma unroll
    for (int nt = 0; nt < 8; nt++)
        #pragma unroll
        for (int i = 0; i < 4; i++) acc[nt][i] = 0.f;

    for (int ks = 0; ks < 8; ks++) {
        const int kc = ks*64;
        __syncthreads();
        for (int k = tid; k < 2048; k += 256) {
            int row = k >> 4, i4 = (k & 15)*4;
            cpa16(&sA[row*68 + i4],
                  &g_attn[(size_t)(m0 + row)*EDIM + kc + i4]);
        }
        cpa_commit();
        for (int k = tid; k < 1024; k += 256) {
            int row = k >> 4, i4 = (k & 15)*4;
            float4 f = *(const float4*)&Wo[(size_t)(n0 + row)*EDIM + kc + i4];
            float hx = tf32r(f.x), hy = tf32r(f.y), hz = tf32r(f.z), hw = tf32r(f.w);
            *(float4*)&sBh[row*68 + i4] = make_float4(hx, hy, hz, hw);
            *(float4*)&sBl[row*68 + i4] = make_float4(
                tf32r(f.x - hx), tf32r(f.y - hy), tf32r(f.z - hz), tf32r(f.w - hw));
        }
        cpa_wait0();
        __syncthreads();

        #pragma unroll
        for (int kk = 0; kk < 8; kk++) {
            const int k0 = kk*8;
            float q0 = sA[mr*68 + k0 + tg];
            float q1 = sA[(mr + 8)*68 + k0 + tg];
            float q2 = sA[mr*68 + k0 + tg + 4];
            float q3 = sA[(mr + 8)*68 + k0 + tg + 4];
            unsigned int ah0 = f2tf32(q0), ah1 = f2tf32(q1);
            unsigned int ah2 = f2tf32(q2), ah3 = f2tf32(q3);
            unsigned int al0 = f2tf32(q0 - __uint_as_float(ah0));
            unsigned int al1 = f2tf32(q1 - __uint_as_float(ah1));
            unsigned int al2 = f2tf32(q2 - __uint_as_float(ah2));
            unsigned int al3 = f2tf32(q3 - __uint_as_float(ah3));
            #pragma unroll
            for (int nt = 0; nt < 8; nt++) {
                const int n = nt*8 + g;
                unsigned int bh0 = __float_as_uint(sBh[n*68 + k0 + tg]);
                unsigned int bh1 = __float_as_uint(sBh[n*68 + k0 + tg + 4]);
                unsigned int bl0 = __float_as_uint(sBl[n*68 + k0 + tg]);
                unsigned int bl1 = __float_as_uint(sBl[n*68 + k0 + tg + 4]);
                mma_tf32(acc[nt], ah0, ah1, ah2, ah3, bh0, bh1);
                mma_tf32(acc[nt], ah0, ah1, ah2, ah3, bl0, bl1);
                mma_tf32(acc[nt], al0, al1, al2, al3, bh0, bh1);
            }
        }
    }

    #pragma unroll
    for (int nt = 0; nt < 8; nt++) {
        const int col = n0 + nt*8 + 2*tg;
        const float b0v = bo[col], b1v = bo[col + 1];
        *(float2*)&out[(size_t)(m0 + mr)*EDIM + col] =
            make_float2(acc[nt][0] + b0v, acc[nt][1] + b1v);
        *(float2*)&out[(size_t)(m0 + mr + 8)*EDIM + col] =
            make_float2(acc[nt][2] + b0v, acc[nt][3] + b1v);
    }
}

// ---------------- launch ----------------
extern "C" void kernel_launch(void* const* d_in, const int* in_sizes, int n_in,
                              void* d_out, int out_size) {
    int idx_x = -1, idx_Er = -1, idx_Wo = -1, idx_bo = -1;
    int cand[8]; int ncand = 0;
    for (int scale = 1; scale <= 4; scale *= 4) {
        idx_x = idx_Er = idx_Wo = idx_bo = -1; ncand = 0;
        for (int i = 0; i < n_in; i++) {
            long long s = in_sizes[i];
            if      (s == (long long)BATCH*TLEN*EDIM*scale)   idx_x  = i;
            else if (s == (long long)HEADS_N*TLEN*SDIM*scale) idx_Er = i;
            else if (s == (long long)EDIM*EDIM*scale)         idx_Wo = i;
            else if (s == (long long)EDIM*scale)              idx_bo = i;
            else if (s == (long long)SDIM*SDIM*scale && ncand < 8) cand[ncand++] = i;
        }
        if (idx_x >= 0 && idx_Er >= 0 && idx_Wo >= 0 && idx_bo >= 0 && ncand == 4)
            break;
    }
    if (!(idx_x >= 0 && idx_Er >= 0 && idx_Wo >= 0 && idx_bo >= 0 && ncand == 4)) {
        int wi = (n_in >= 9) ? 3 : 2;
        idx_x = 0; cand[0] = 1; cand[1] = wi; cand[2] = wi + 1; cand[3] = wi + 2;
        idx_Er = wi + 3; idx_Wo = wi + 4; idx_bo = wi + 5; ncand = 4;
    }

    const float* x  = (const float*)d_in[idx_x];
    const float* Er = (const float*)d_in[idx_Er];
    const float* Wo = (const float*)d_in[idx_Wo];
    const float* bo = (const float*)d_in[idx_bo];
    float* out = (float*)d_out;

    const int PROJ_SMEM = (256*68) * (int)sizeof(float);            // 69632 B
    const int ATTN_SMEM = (4*64*AST) * (int)sizeof(float);          // 69632 B
    const int RG_SMEM   = (4*64*68) * (int)sizeof(float);           // 69632 B
    const int OP_SMEM   = (256*68) * (int)sizeof(float);            // 69632 B
    cudaFuncSetAttribute(proj_kernel, cudaFuncAttributeMaxDynamicSharedMemorySize, PROJ_SMEM);
    cudaFuncSetAttribute(attn_part_kernel, cudaFuncAttributeMaxDynamicSharedMemorySize, ATTN_SMEM);
    cudaFuncSetAttribute(relgemm_kernel, cudaFuncAttributeMaxDynamicSharedMemorySize, RG_SMEM);
    cudaFuncSetAttribute(outproj_kernel, cudaFuncAttributeMaxDynamicSharedMemorySize, OP_SMEM);

    select_inputs<<<1, 256>>>((const float*)d_in[cand[0]], (const float*)d_in[cand[1]],
                              (const float*)d_in[cand[2]], (const float*)d_in[cand[3]],
                              (idx_x == 0) ? 1 : 0);
    proj_kernel<<<dim3(TLEN/128, 3*HEADS_N, BATCH), 256, PROJ_SMEM>>>(x);
    relgemm_kernel<<<dim3(NCHUNK + 1, HEADS_N, BATCH), 256, RG_SMEM>>>(Er);
    attn_part_kernel<<<dim3(NCHUNK, HEADS_N, BATCH), 128, ATTN_SMEM>>>();
    reduce_kernel<<<dim3(TLEN/64, HEADS_N, BATCH), 128>>>();
    outproj_kernel<<<dim3((BATCH*TLEN)/128, EDIM/64), 256, OP_SMEM>>>(Wo, bo, out);
}

// round 17
// speedup vs baseline: 1.1328x; 1.0299x over previous
#include <cuda_runtime.h>
#include <math.h>

#define TLEN    2048
#define HEADS_N 8
#define BATCH   2
#define SDIM    64
#define EDIM    512
#define QE_BH   2162688   // 4096 * 528 floats per (b,h)
#define NCHUNK  144       // sum over it of ceil((it+1)/4)

// ---------------- scratch + resolved input pointers (device-resident) ----------
__device__ float g_q[BATCH*HEADS_N*TLEN*SDIM];
__device__ float g_k[BATCH*HEADS_N*TLEN*SDIM];   // tf32-rounded, pre-scaled 512^-0.5
__device__ float g_v[BATCH*HEADS_N*TLEN*SDIM];   // tf32-rounded
__device__ float g_vmean[BATCH*HEADS_N*SDIM];
__device__ float g_attn[BATCH*TLEN*EDIM];
__device__ float g_qe[BATCH*HEADS_N*QE_BH];   // triangular-packed QE bands
__device__ float g_pO[(size_t)BATCH*HEADS_N*NCHUNK*64*64];   // split-KV partials
__device__ float g_pm[BATCH*HEADS_N*NCHUNK*64];
__device__ float g_pl[BATCH*HEADS_N*NCHUNK*64];

__device__ const float*        g_pWq;
__device__ const float*        g_pWk;
__device__ const float*        g_pWv;
__device__ const unsigned int* g_pmask;

// ---------------- tf32 + cp.async helpers ----------------
__device__ __forceinline__ unsigned int f2tf32(float x) {
    unsigned int r;
    asm("cvt.rna.tf32.f32 %0, %1;" : "=r"(r) : "f"(x));
    return r;
}
__device__ __forceinline__ float tf32r(float x) {
    return __uint_as_float(f2tf32(x));
}
__device__ __forceinline__ void mma_tf32(float d[4],
        unsigned int a0, unsigned int a1, unsigned int a2, unsigned int a3,
        unsigned int b0, unsigned int b1) {
    asm("mma.sync.aligned.m16n8k8.row.col.f32.tf32.tf32.f32 "
        "{%0,%1,%2,%3}, {%4,%5,%6,%7}, {%8,%9}, {%0,%1,%2,%3};"
        : "+f"(d[0]), "+f"(d[1]), "+f"(d[2]), "+f"(d[3])
        : "r"(a0), "r"(a1), "r"(a2), "r"(a3), "r"(b0), "r"(b1));
}
__device__ __forceinline__ void cpa16(void* s, const void* g) {
    unsigned int sa = (unsigned int)__cvta_generic_to_shared(s);
    asm volatile("cp.async.cg.shared.global [%0], [%1], 16;" :: "r"(sa), "l"(g));
}
__device__ __forceinline__ void cpa_commit() {
    asm volatile("cp.async.commit_group;");
}
__device__ __forceinline__ void cpa_wait0() {
    asm volatile("cp.async.wait_group 0;");
}

// ---------------- prologue: content-based identification of mask ---------------
__global__ void select_inputs(const float* c0, const float* c1,
                              const float* c2, const float* c3, int x_first) {
    __shared__ int bad[4];
    const float* cand[4] = {c0, c1, c2, c3};
    if (threadIdx.x < 4) bad[threadIdx.x] = 0;
    __syncthreads();
    for (int j = 0; j < 4; j++) {
        const unsigned int* p = (const unsigned int*)cand[j];
        int b = 0;
        for (int i = threadIdx.x; i < 512; i += blockDim.x) {
            unsigned int v = p[i];
            if (v != 0u && v != 1u && v != 0x3F800000u) { b = 1; break; }
        }
        if (b) atomicOr(&bad[j], 1);
    }
    __syncthreads();
    if (threadIdx.x == 0) {
        int mi = -1;
        for (int j = 0; j < 4; j++) if (!bad[j]) { mi = j; break; }
        if (mi < 0) mi = x_first ? 0 : 3;
        const float* rest[3]; int n = 0;
        for (int j = 0; j < 4; j++) if (j != mi) rest[n++] = cand[j];
        g_pmask = (const unsigned int*)cand[mi];
        if (x_first) { g_pWq = rest[0]; g_pWk = rest[1]; g_pWv = rest[2]; }
        else         { g_pWk = rest[0]; g_pWq = rest[1]; g_pWv = rest[2]; }
    }
}

// ---------------- QKV projection via tf32 3x mma ----------------
// K output: tf32r(k * 512^-0.5); V output: tf32r(v); Q output: fp32.
__global__ void __launch_bounds__(256) proj_kernel(const float* __restrict__ x) {
    extern __shared__ float sm[];
    float* sX = sm;              // [row=128][k=64] fp32, stride 68
    float* sWh = sX + 128*68;    // [o=64][k] hi
    float* sWl = sWh + 64*68;    // lo

    const int m0 = blockIdx.x * 128;
    const int h  = blockIdx.y / 3;
    const int mm = blockIdx.y % 3;
    const int b  = blockIdx.z;
    const int tid = threadIdx.x;
    const float* W = (mm == 0) ? g_pWq : (mm == 1) ? g_pWk : g_pWv;
    float* dst = (mm == 0) ? g_q : (mm == 1) ? g_k : g_v;

    for (int k = tid; k < 2048; k += 256) {
        int row = k >> 4, i4 = (k & 15)*4;
        cpa16(&sX[row*68 + i4],
              &x[(size_t)(b*TLEN + m0 + row)*EDIM + h*SDIM + i4]);
    }
    cpa_commit();
    for (int k = tid; k < 1024; k += 256) {
        int row = k >> 4, i4 = (k & 15)*4;
        float4 f = *(const float4*)&W[row*SDIM + i4];
        float hx = tf32r(f.x), hy = tf32r(f.y), hz = tf32r(f.z), hw = tf32r(f.w);
        *(float4*)&sWh[row*68 + i4] = make_float4(hx, hy, hz, hw);
        *(float4*)&sWl[row*68 + i4] = make_float4(
            tf32r(f.x - hx), tf32r(f.y - hy), tf32r(f.z - hz), tf32r(f.w - hw));
    }
    cpa_wait0();
    __syncthreads();

    const int w = tid >> 5, lane = tid & 31;
    const int g = lane >> 2, tg = lane & 3;
    const int mr = w*16 + g;

    float acc[8][4];
    #pragma unroll
    for (int nt = 0; nt < 8; nt++)
        #pragma unroll
        for (int i = 0; i < 4; i++) acc[nt][i] = 0.f;

    #pragma unroll
    for (int kk = 0; kk < 8; kk++) {
        const int k0 = kk*8;
        float q0 = sX[mr*68 + k0 + tg];
        float q1 = sX[(mr + 8)*68 + k0 + tg];
        float q2 = sX[mr*68 + k0 + tg + 4];
        float q3 = sX[(mr + 8)*68 + k0 + tg + 4];
        unsigned int ah0 = f2tf32(q0), ah1 = f2tf32(q1);
        unsigned int ah2 = f2tf32(q2), ah3 = f2tf32(q3);
        unsigned int al0 = f2tf32(q0 - __uint_as_float(ah0));
        unsigned int al1 = f2tf32(q1 - __uint_as_float(ah1));
        unsigned int al2 = f2tf32(q2 - __uint_as_float(ah2));
        unsigned int al3 = f2tf32(q3 - __uint_as_float(ah3));
        #pragma unroll
        for (int nt = 0; nt < 8; nt++) {
            const int n = nt*8 + g;
            unsigned int bh0 = __float_as_uint(sWh[n*68 + k0 + tg]);
            unsigned int bh1 = __float_as_uint(sWh[n*68 + k0 + tg + 4]);
            unsigned int bl0 = __float_as_uint(sWl[n*68 + k0 + tg]);
            unsigned int bl1 = __float_as_uint(sWl[n*68 + k0 + tg + 4]);
            mma_tf32(acc[nt], ah0, ah1, ah2, ah3, bh0, bh1);
            mma_tf32(acc[nt], ah0, ah1, ah2, ah3, bl0, bl1);
            mma_tf32(acc[nt], al0, al1, al2, al3, bh0, bh1);
        }
    }

    const float scale2 = 0.04419417382415922f;   // 512^-0.5
    const size_t bh = (size_t)(b*HEADS_N + h);
    #pragma unroll
    for (int nt = 0; nt < 8; nt++) {
        const int col = nt*8 + 2*tg;
        float v0 = acc[nt][0], v1 = acc[nt][1];
        float v2 = acc[nt][2], v3 = acc[nt][3];
        if (mm == 1) {
            v0 = tf32r(v0*scale2); v1 = tf32r(v1*scale2);
            v2 = tf32r(v2*scale2); v3 = tf32r(v3*scale2);
        } else if (mm == 2) {
            v0 = tf32r(v0); v1 = tf32r(v1);
            v2 = tf32r(v2); v3 = tf32r(v3);
        }
        *(float2*)&dst[(bh*TLEN + m0 + mr)*SDIM + col] = make_float2(v0, v1);
        *(float2*)&dst[(bh*TLEN + m0 + mr + 8)*SDIM + col] = make_float2(v2, v3);
    }
}

// ---------------- rel-pos GEMM v2: chunked, natural-layout B ----------------
__global__ void __launch_bounds__(256) relgemm_kernel(const float* __restrict__ Er) {
    extern __shared__ float sm[];
    const int tid = threadIdx.x;
    const int h = blockIdx.y, b = blockIdx.z;

    if (blockIdx.x == NCHUNK) {   // fused V-mean for (b,h)
        const int bh = b*HEADS_N + h;
        const int d = tid & 63, sub = tid >> 6;
        float a = 0.f;
        for (int l = sub; l < TLEN; l += 4)
            a += g_v[((size_t)bh*TLEN + l)*SDIM + d];
        sm[sub*64 + d] = a;
        __syncthreads();
        if (sub == 0)
            g_vmean[bh*SDIM + d] =
                (sm[d] + sm[64 + d] + sm[128 + d] + sm[192 + d]) * (1.f/(float)TLEN);
        return;
    }

    float* Qh = sm;              // [m=64][k] stride 68
    float* Ql = Qh + 64*68;
    float* Eh = Ql + 64*68;      // [n=o][k=s] natural rows, stride 68
    float* El = Eh + 64*68;

    const int x = (int)blockIdx.x;
    int it = 31, cb = 0;
    {
        int base = 0;
        for (int k = 0; k < 32; k++) {
            int nch = (k + 4) >> 2;
            if (x < base + nch) { it = k; cb = base; break; }
            base += nch;
        }
    }
    const int chunk = x - cb;
    const int osta = chunk*4;
    const int oend = min(osta + 4, it + 1);
    const int i0 = it * 64;

    const float* gq = g_q + (size_t)(b*HEADS_N + h)*TLEN*SDIM + (size_t)i0*SDIM;
    const float* ge = Er + (size_t)h*TLEN*SDIM;

    #pragma unroll
    for (int kk = 0; kk < 4; kk++) {
        int k = kk*256 + tid;
        int m = k >> 4, s4 = (k & 15)*4;
        float4 f = *(const float4*)&gq[m*SDIM + s4];
        float hx = tf32r(f.x), hy = tf32r(f.y), hz = tf32r(f.z), hw = tf32r(f.w);
        *(float4*)&Qh[m*68 + s4] = make_float4(hx, hy, hz, hw);
        *(float4*)&Ql[m*68 + s4] = make_float4(
            tf32r(f.x - hx), tf32r(f.y - hy), tf32r(f.z - hz), tf32r(f.w - hw));
    }

    const int w = tid >> 5, lane = tid & 31;
    const int g = lane >> 2, tg = lane & 3;
    const int mr = (w & 3)*16 + g;
    const int nb = (w >> 2)*32;

    const int W = 64*(it + 1);
    float* qb = g_qe + (size_t)(b*HEADS_N + h)*QE_BH + (size_t)4096*(it*(it + 1)/2);

    for (int oc = osta; oc < oend; oc++) {
        const int j0 = TLEN - 64 - i0 + oc*64;
        __syncthreads();
        #pragma unroll
        for (int kk = 0; kk < 4; kk++) {
            int k = kk*256 + tid;
            int o = k >> 4, s4 = (k & 15)*4;
            float4 f = *(const float4*)&ge[(size_t)(j0 + o)*SDIM + s4];
            float hx = tf32r(f.x), hy = tf32r(f.y), hz = tf32r(f.z), hw = tf32r(f.w);
            *(float4*)&Eh[o*68 + s4] = make_float4(hx, hy, hz, hw);
            *(float4*)&El[o*68 + s4] = make_float4(
                tf32r(f.x - hx), tf32r(f.y - hy), tf32r(f.z - hz), tf32r(f.w - hw));
        }
        __syncthreads();

        float d[4][4];
        #pragma unroll
        for (int nt = 0; nt < 4; nt++)
            #pragma unroll
            for (int i = 0; i < 4; i++) d[nt][i] = 0.f;

        #pragma unroll
        for (int kk = 0; kk < 8; kk++) {
            const int k0 = kk*8;
            unsigned int ah0 = __float_as_uint(Qh[mr*68 + k0 + tg]);
            unsigned int ah1 = __float_as_uint(Qh[(mr + 8)*68 + k0 + tg]);
            unsigned int ah2 = __float_as_uint(Qh[mr*68 + k0 + tg + 4]);
            unsigned int ah3 = __float_as_uint(Qh[(mr + 8)*68 + k0 + tg + 4]);
            unsigned int al0 = __float_as_uint(Ql[mr*68 + k0 + tg]);
            unsigned int al1 = __float_as_uint(Ql[(mr + 8)*68 + k0 + tg]);
            unsigned int al2 = __float_as_uint(Ql[mr*68 + k0 + tg + 4]);
            unsigned int al3 = __float_as_uint(Ql[(mr + 8)*68 + k0 + tg + 4]);
            #pragma unroll
            for (int nt = 0; nt < 4; nt++) {
                const int n = nb + nt*8 + g;
                unsigned int bh0 = __float_as_uint(Eh[n*68 + k0 + tg]);
                unsigned int bh1 = __float_as_uint(Eh[n*68 + k0 + tg + 4]);
                unsigned int bl0 = __float_as_uint(El[n*68 + k0 + tg]);
                unsigned int bl1 = __float_as_uint(El[n*68 + k0 + tg + 4]);
                mma_tf32(d[nt], ah0, ah1, ah2, ah3, bh0, bh1);
                mma_tf32(d[nt], ah0, ah1, ah2, ah3, bl0, bl1);
                mma_tf32(d[nt], al0, al1, al2, al3, bh0, bh1);
            }
        }

        const int colb = oc*64 + nb;
        #pragma unroll
        for (int nt = 0; nt < 4; nt++) {
            const int col = colb + nt*8 + 2*tg;
            *(float2*)&qb[(size_t)mr*W + col]       = make_float2(d[nt][0], d[nt][1]);
            *(float2*)&qb[(size_t)(mr + 8)*W + col] = make_float2(d[nt][2], d[nt][3]);
        }
    }
}

// ---------------- split-KV tensor-core flash attention (partials) ---------------
// 128 threads = 4 warps. K,V pre-rounded (K pre-scaled). cp.async staging.
// QK = Qhi * Khi (1-term), PV = (Phi+Plo) * Vhi (2-term).
#define AST 68   // 68 mod 32 == 4 -> all fragment LDS conflict-free
__global__ void __launch_bounds__(128, 3) attn_part_kernel() {
    extern __shared__ float sm[];
    float* sQ = sm;              // [i][s]  64 x AST  fp32
    float* sK = sQ + 64*AST;     // [c][s]  tf32-hi, pre-scaled
    float* sV = sK + 64*AST;     // [lc][d] tf32-hi
    float* sP = sV + 64*AST;     // [i][lc] fp32

    const int x = NCHUNK - 1 - (int)blockIdx.x;   // heavy i-tiles first
    int it = 31, cb = 0;
    {
        int base = 0;
        for (int k = 0; k < 32; k++) {
            int nch = (k + 4) >> 2;
            if (x < base + nch) { it = k; cb = base; break; }
            base += nch;
        }
    }
    const int chunk = x - cb;
    const int csta = chunk*4;
    const int cend = min(csta + 4, it + 1);
    const int i0 = it * 64;

    const int h  = blockIdx.y;
    const int b  = blockIdx.z;
    const int tid = threadIdx.x;
    const int w = tid >> 5, lane = tid & 31;
    const int g = lane >> 2, tg = lane & 3;
    const int rA = w*16 + g, rB = rA + 8;

    const size_t bh = (size_t)(b*HEADS_N + h);
    const float* gq = g_q + bh*TLEN*SDIM;
    const float* gk = g_k + bh*TLEN*SDIM;
    const float* gv = g_v + bh*TLEN*SDIM;

    const int Wqe = 64*(it + 1);
    const float* qeb = g_qe + bh*QE_BH + (size_t)4096*(it*(it + 1)/2);
    const int omax = i0 + 63;

    // stage Q via cp.async (fp32, unscaled — scale lives in g_k)
    for (int k = tid; k < 1024; k += 128) {
        int li = k >> 4, s4 = (k & 15)*4;
        cpa16(&sQ[li*AST + s4], &gq[(size_t)(i0 + li)*SDIM + s4]);
    }
    cpa_commit();

    float mA = -1e30f, mB = -1e30f, lA = 0.f, lB = 0.f;
    float O[8][4];
    #pragma unroll
    for (int nt = 0; nt < 8; nt++)
        #pragma unroll
        for (int i = 0; i < 4; i++) O[nt][i] = 0.f;

    for (int ct = csta; ct < cend; ct++) {
        const int c0 = ct * 64;
        __syncthreads();   // prev tile fully consumed
        for (int k = tid; k < 1024; k += 128) {
            int li = k >> 4, s4 = (k & 15)*4;
            cpa16(&sK[li*AST + s4], &gk[(size_t)(c0 + li)*SDIM + s4]);
            cpa16(&sV[li*AST + s4], &gv[(size_t)(c0 + li)*SDIM + s4]);
        }
        cpa_commit();
        cpa_wait0();       // also covers the Q group on first iteration
        __syncthreads();

        float acc[8][4];
        #pragma unroll
        for (int nt = 0; nt < 8; nt++)
            #pragma unroll
            for (int i = 0; i < 4; i++) acc[nt][i] = 0.f;

        // ---- S = Q K^T : Qhi * Khi (1-term) ----
        #pragma unroll
        for (int kk = 0; kk < 8; kk++) {
            const int k0 = kk*8;
            unsigned int ah0 = f2tf32(sQ[rA*AST + k0 + tg]);
            unsigned int ah1 = f2tf32(sQ[rB*AST + k0 + tg]);
            unsigned int ah2 = f2tf32(sQ[rA*AST + k0 + tg + 4]);
            unsigned int ah3 = f2tf32(sQ[rB*AST + k0 + tg + 4]);
            #pragma unroll
            for (int nt = 0; nt < 8; nt++) {
                const int n = nt*8 + g;
                unsigned int bh0 = __float_as_uint(sK[n*AST + k0 + tg]);
                unsigned int bh1 = __float_as_uint(sK[n*AST + k0 + tg + 4]);
                mma_tf32(acc[nt], ah0, ah1, ah2, ah3, bh0, bh1);
            }
        }

        #pragma unroll
        for (int nt = 0; nt < 8; nt++) {
            const int cl = nt*8 + 2*tg;
            const int oA = 63 - rA + c0 + cl;
            const int oB = 63 - rB + c0 + cl;
            if (oA     <= omax) acc[nt][0] += __ldg(qeb + (size_t)rA*Wqe + oA);
            if (oA + 1 <= omax) acc[nt][1] += __ldg(qeb + (size_t)rA*Wqe + oA + 1);
            if (oB     <= omax) acc[nt][2] += __ldg(qeb + (size_t)rB*Wqe + oB);
            if (oB + 1 <= omax) acc[nt][3] += __ldg(qeb + (size_t)rB*Wqe + oB + 1);
            if (ct == it) {
                if (cl     > rA) acc[nt][0] = -1e30f;
                if (cl + 1 > rA) acc[nt][1] = -1e30f;
                if (cl     > rB) acc[nt][2] = -1e30f;
                if (cl + 1 > rB) acc[nt][3] = -1e30f;
            }
        }

        float mxA = -1e30f, mxB = -1e30f;
        #pragma unroll
        for (int nt = 0; nt < 8; nt++) {
            mxA = fmaxf(mxA, fmaxf(acc[nt][0], acc[nt][1]));
            mxB = fmaxf(mxB, fmaxf(acc[nt][2], acc[nt][3]));
        }
        mxA = fmaxf(mxA, __shfl_xor_sync(0xffffffffu, mxA, 1));
        mxA = fmaxf(mxA, __shfl_xor_sync(0xffffffffu, mxA, 2));
        mxB = fmaxf(mxB, __shfl_xor_sync(0xffffffffu, mxB, 1));
        mxB = fmaxf(mxB, __shfl_xor_sync(0xffffffffu, mxB, 2));
        const float mnA = fmaxf(mA, mxA), mnB = fmaxf(mB, mxB);
        const float cA = __expf(mA - mnA), cB = __expf(mB - mnB);
        float sA = 0.f, sB = 0.f;
        #pragma unroll
        for (int nt = 0; nt < 8; nt++) {
            acc[nt][0] = __expf(acc[nt][0] - mnA);
            acc[nt][1] = __expf(acc[nt][1] - mnA);
            acc[nt][2] = __expf(acc[nt][2] - mnB);
            acc[nt][3] = __expf(acc[nt][3] - mnB);
            sA += acc[nt][0] + acc[nt][1];
            sB += acc[nt][2] + acc[nt][3];
        }
        sA += __shfl_xor_sync(0xffffffffu, sA, 1);
        sA += __shfl_xor_sync(0xffffffffu, sA, 2);
        sB += __shfl_xor_sync(0xffffffffu, sB, 1);
        sB += __shfl_xor_sync(0xffffffffu, sB, 2);
        lA = lA*cA + sA;  mA = mnA;
        lB = lB*cB + sB;  mB = mnB;
        #pragma unroll
        for (int nt = 0; nt < 8; nt++) {
            O[nt][0] *= cA; O[nt][1] *= cA;
            O[nt][2] *= cB; O[nt][3] *= cB;
        }

        #pragma unroll
        for (int nt = 0; nt < 8; nt++) {
            *(float2*)&sP[rA*AST + nt*8 + 2*tg] = make_float2(acc[nt][0], acc[nt][1]);
            *(float2*)&sP[rB*AST + nt*8 + 2*tg] = make_float2(acc[nt][2], acc[nt][3]);
        }
        __syncwarp();

        // ---- O += P V : (Phi + Plo) * Vhi ----
        #pragma unroll
        for (int kk = 0; kk < 8; kk++) {
            const int k0 = kk*8;
            float p0 = sP[rA*AST + k0 + tg];
            float p1 = sP[rB*AST + k0 + tg];
            float p2 = sP[rA*AST + k0 + tg + 4];
            float p3 = sP[rB*AST + k0 + tg + 4];
            unsigned int ah0 = f2tf32(p0), ah1 = f2tf32(p1);
            unsigned int ah2 = f2tf32(p2), ah3 = f2tf32(p3);
            unsigned int al0 = f2tf32(p0 - __uint_as_float(ah0));
            unsigned int al1 = f2tf32(p1 - __uint_as_float(ah1));
            unsigned int al2 = f2tf32(p2 - __uint_as_float(ah2));
            unsigned int al3 = f2tf32(p3 - __uint_as_float(ah3));
            #pragma unroll
            for (int nt = 0; nt < 8; nt++) {
                const int n = nt*8 + g;
                unsigned int bh0 = __float_as_uint(sV[(k0 + tg)*AST + n]);
                unsigned int bh1 = __float_as_uint(sV[(k0 + tg + 4)*AST + n]);
                mma_tf32(O[nt], ah0, ah1, ah2, ah3, bh0, bh1);
                mma_tf32(O[nt], al0, al1, al2, al3, bh0, bh1);
            }
        }
    }

    const int slot = (int)(bh*NCHUNK) + cb + chunk;
    float* pO = g_pO + (size_t)slot*64*64;
    #pragma unroll
    for (int nt = 0; nt < 8; nt++) {
        *(float2*)&pO[rA*64 + nt*8 + 2*tg] = make_float2(O[nt][0], O[nt][1]);
        *(float2*)&pO[rB*64 + nt*8 + 2*tg] = make_float2(O[nt][2], O[nt][3]);
    }
    if (tg == 0) {
        g_pm[slot*64 + rA] = mA;  g_pl[slot*64 + rA] = lA;
        g_pm[slot*64 + rB] = mB;  g_pl[slot*64 + rB] = lB;
    }
}

// ---------------- split-KV reduce: merge partials, mask, scramble --------------
__global__ void __launch_bounds__(128) reduce_kernel() {
    const int it = blockIdx.x, h = blockIdx.y, b = blockIdx.z;
    int base = 0;
    for (int k = 0; k < it; k++) base += (k + 4) >> 2;
    const int nc = (it + 4) >> 2;
    const int slot0 = (b*HEADS_N + h)*NCHUNK + base;
    const int tid = threadIdx.x;
    const int row = tid >> 1;
    const int half = (tid & 1)*32;

    float mstar = -1e30f;
    for (int p = 0; p < nc; p++)
        mstar = fmaxf(mstar, g_pm[(slot0 + p)*64 + row]);

    float lstar = 0.f;
    float Oa[32];
    #pragma unroll
    for (int d = 0; d < 32; d++) Oa[d] = 0.f;

    for (int p = 0; p < nc; p++) {
        const float f = __expf(g_pm[(slot0 + p)*64 + row] - mstar);
        lstar += g_pl[(slot0 + p)*64 + row] * f;
        const float* po = g_pO + ((size_t)(slot0 + p)*64 + row)*64 + half;
        #pragma unroll
        for (int d4 = 0; d4 < 8; d4++) {
            float4 v = *(const float4*)&po[d4*4];
            Oa[d4*4 + 0] += f*v.x;
            Oa[d4*4 + 1] += f*v.y;
            Oa[d4*4 + 2] += f*v.z;
            Oa[d4*4 + 3] += f*v.w;
        }
    }

    const int i = it*64 + row;
    const unsigned int mk = g_pmask[b*TLEN + i];
    const float inv = 1.f / lstar;
    float* dst = &g_attn[((size_t)(b*TLEN) + h*256 + (i >> 3))*EDIM
                         + ((i & 7) << 6) + half];
    if (mk != 0u) {
        #pragma unroll
        for (int d = 0; d < 32; d++) dst[d] = Oa[d]*inv;
    } else {
        const float* vm = &g_vmean[(b*HEADS_N + h)*SDIM + half];
        #pragma unroll
        for (int d = 0; d < 32; d++) dst[d] = vm[d];
    }
}

// ---------------- output projection via tf32 3x mma ----------------------------
__global__ void __launch_bounds__(256) outproj_kernel(const float* __restrict__ Wo,
                                                      const float* __restrict__ bo,
                                                      float* __restrict__ out) {
    extern __shared__ float sm[];
    float* sA  = sm;             // [row=128][k=64] fp32, stride 68
    float* sBh = sA + 128*68;    // [n=64][k] hi
    float* sBl = sBh + 64*68;    // lo

    const int m0 = blockIdx.x * 128;
    const int n0 = blockIdx.y * 64;
    const int tid = threadIdx.x;
    const int w = tid >> 5, lane = tid & 31;
    const int g = lane >> 2, tg = lane & 3;
    const int mr = w*16 + g;

    float acc[8][4];
    #pragma unroll
    for (int nt = 0; nt < 8; nt++)
        #pragma unroll
        for (int i = 0; i < 4; i++) acc[nt][i] = 0.f;

    for (int ks = 0; ks < 8; ks++) {
        const int kc = ks*64;
        __syncthreads();
        for (int k = tid; k < 2048; k += 256) {
            int row = k >> 4, i4 = (k & 15)*4;
            cpa16(&sA[row*68 + i4],
                  &g_attn[(size_t)(m0 + row)*EDIM + kc + i4]);
        }
        cpa_commit();
        for (int k = tid; k < 1024; k += 256) {
            int row = k >> 4, i4 = (k & 15)*4;
            float4 f = *(const float4*)&Wo[(size_t)(n0 + row)*EDIM + kc + i4];
            float hx = tf32r(f.x), hy = tf32r(f.y), hz = tf32r(f.z), hw = tf32r(f.w);
            *(float4*)&sBh[row*68 + i4] = make_float4(hx, hy, hz, hw);
            *(float4*)&sBl[row*68 + i4] = make_float4(
                tf32r(f.x - hx), tf32r(f.y - hy), tf32r(f.z - hz), tf32r(f.w - hw));
        }
        cpa_wait0();
        __syncthreads();

        #pragma unroll
        for (int kk = 0; kk < 8; kk++) {
            const int k0 = kk*8;
            float q0 = sA[mr*68 + k0 + tg];
            float q1 = sA[(mr + 8)*68 + k0 + tg];
            float q2 = sA[mr*68 + k0 + tg + 4];
            float q3 = sA[(mr + 8)*68 + k0 + tg + 4];
            unsigned int ah0 = f2tf32(q0), ah1 = f2tf32(q1);
            unsigned int ah2 = f2tf32(q2), ah3 = f2tf32(q3);
            unsigned int al0 = f2tf32(q0 - __uint_as_float(ah0));
            unsigned int al1 = f2tf32(q1 - __uint_as_float(ah1));
            unsigned int al2 = f2tf32(q2 - __uint_as_float(ah2));
            unsigned int al3 = f2tf32(q3 - __uint_as_float(ah3));
            #pragma unroll
            for (int nt = 0; nt < 8; nt++) {
                const int n = nt*8 + g;
                unsigned int bh0 = __float_as_uint(sBh[n*68 + k0 + tg]);
                unsigned int bh1 = __float_as_uint(sBh[n*68 + k0 + tg + 4]);
                unsigned int bl0 = __float_as_uint(sBl[n*68 + k0 + tg]);
                unsigned int bl1 = __float_as_uint(sBl[n*68 + k0 + tg + 4]);
                mma_tf32(acc[nt], ah0, ah1, ah2, ah3, bh0, bh1);
                mma_tf32(acc[nt], ah0, ah1, ah2, ah3, bl0, bl1);
                mma_tf32(acc[nt], al0, al1, al2, al3, bh0, bh1);
            }
        }
    }

    #pragma unroll
    for (int nt = 0; nt < 8; nt++) {
        const int col = n0 + nt*8 + 2*tg;
        const float b0v = bo[col], b1v = bo[col + 1];
        *(float2*)&out[(size_t)(m0 + mr)*EDIM + col] =
            make_float2(acc[nt][0] + b0v, acc[nt][1] + b1v);
        *(float2*)&out[(size_t)(m0 + mr + 8)*EDIM + col] =
            make_float2(acc[nt][2] + b0v, acc[nt][3] + b1v);
    }
}

// ---------------- launch ----------------
extern "C" void kernel_launch(void* const* d_in, const int* in_sizes, int n_in,
                              void* d_out, int out_size) {
    int idx_x = -1, idx_Er = -1, idx_Wo = -1, idx_bo = -1;
    int cand[8]; int ncand = 0;
    for (int scale = 1; scale <= 4; scale *= 4) {
        idx_x = idx_Er = idx_Wo = idx_bo = -1; ncand = 0;
        for (int i = 0; i < n_in; i++) {
            long long s = in_sizes[i];
            if      (s == (long long)BATCH*TLEN*EDIM*scale)   idx_x  = i;
            else if (s == (long long)HEADS_N*TLEN*SDIM*scale) idx_Er = i;
            else if (s == (long long)EDIM*EDIM*scale)         idx_Wo = i;
            else if (s == (long long)EDIM*scale)              idx_bo = i;
            else if (s == (long long)SDIM*SDIM*scale && ncand < 8) cand[ncand++] = i;
        }
        if (idx_x >= 0 && idx_Er >= 0 && idx_Wo >= 0 && idx_bo >= 0 && ncand == 4)
            break;
    }
    if (!(idx_x >= 0 && idx_Er >= 0 && idx_Wo >= 0 && idx_bo >= 0 && ncand == 4)) {
        int wi = (n_in >= 9) ? 3 : 2;
        idx_x = 0; cand[0] = 1; cand[1] = wi; cand[2] = wi + 1; cand[3] = wi + 2;
        idx_Er = wi + 3; idx_Wo = wi + 4; idx_bo = wi + 5; ncand = 4;
    }

    const float* x  = (const float*)d_in[idx_x];
    const float* Er = (const float*)d_in[idx_Er];
    const float* Wo = (const float*)d_in[idx_Wo];
    const float* bo = (const float*)d_in[idx_bo];
    float* out = (float*)d_out;

    const int PROJ_SMEM = (256*68) * (int)sizeof(float);            // 69632 B
    const int ATTN_SMEM = (4*64*AST) * (int)sizeof(float);          // 69632 B
    const int RG_SMEM   = (4*64*68) * (int)sizeof(float);           // 69632 B
    const int OP_SMEM   = (256*68) * (int)sizeof(float);            // 69632 B
    cudaFuncSetAttribute(proj_kernel, cudaFuncAttributeMaxDynamicSharedMemorySize, PROJ_SMEM);
    cudaFuncSetAttribute(attn_part_kernel, cudaFuncAttributeMaxDynamicSharedMemorySize, ATTN_SMEM);
    cudaFuncSetAttribute(relgemm_kernel, cudaFuncAttributeMaxDynamicSharedMemorySize, RG_SMEM);
    cudaFuncSetAttribute(outproj_kernel, cudaFuncAttributeMaxDynamicSharedMemorySize, OP_SMEM);

    select_inputs<<<1, 256>>>((const float*)d_in[cand[0]], (const float*)d_in[cand[1]],
                              (const float*)d_in[cand[2]], (const float*)d_in[cand[3]],
                              (idx_x == 0) ? 1 : 0);
    proj_kernel<<<dim3(TLEN/128, 3*HEADS_N, BATCH), 256, PROJ_SMEM>>>(x);
    relgemm_kernel<<<dim3(NCHUNK + 1, HEADS_N, BATCH), 256, RG_SMEM>>>(Er);
    attn_part_kernel<<<dim3(NCHUNK, HEADS_N, BATCH), 128, ATTN_SMEM>>>();
    reduce_kernel<<<dim3(TLEN/64, HEADS_N, BATCH), 128>>>();
    outproj_kernel<<<dim3((BATCH*TLEN)/128, EDIM/64), 256, OP_SMEM>>>(Wo, bo, out);
}